// round 10
// baseline (speedup 1.0000x reference)
#include <cuda_runtime.h>
#include <cuda_fp16.h>
#include <cstdint>

#define T_SEQ 2048
#define HID   4096
#define QKV_N 6144
#define HD    128
#define NHEADS 32
#define ATTN_SCALE 0.08838834764831845f   // 128^-0.5

// GEMM: BM=BN=128, BK=64 (fp16), tiles Ah/Al/B 16KB each (128 rows x 128B),
// 2-stage cp.async pipeline, 2 CTAs/SM.
#define GTILE 16384
#define GSTG  (3 * GTILE)          // 48KB per stage
#define GEMM_SMEM (2 * GSTG)       // 96KB

// Attention v3: Q 128x128 hi/lo (64KB) + 2-stage KV (2x64KB) + P 128x64 (16KB)
#define AQH 0
#define AQL 32768
#define AKV 65536          // stage s at AKV + s*65536: Kh,Kl,Vh,Vl 16KB each
#define APS (AKV + 2 * 65536)
#define ATTN_SMEM (APS + 16384)   // 212992

extern __shared__ char dyn_smem[];

// ---------------------------------------------------------------------------
// Scratch (allocation-free rule: __device__ globals)
// ---------------------------------------------------------------------------
__device__ float g_qkv[(size_t)T_SEQ * QKV_N];
__device__ __align__(16) __half g_ah[(size_t)T_SEQ * HID];    // GEMM A hi
__device__ __align__(16) __half g_al[(size_t)T_SEQ * HID];    // GEMM A lo
__device__ __align__(16) __half g_wqh[(size_t)QKV_N * HID];   // Wqkv^T fp16 [N,K]
__device__ __align__(16) __half g_woh[(size_t)HID * HID];     // Wo^T fp16
__device__ __align__(16) __half g_qh[(size_t)T_SEQ * HID];    // roped+scaled Q hi
__device__ __align__(16) __half g_ql[(size_t)T_SEQ * HID];
__device__ __align__(16) __half g_kh[(size_t)T_SEQ * 1024];   // roped K hi
__device__ __align__(16) __half g_kl[(size_t)T_SEQ * 1024];
__device__ __align__(16) __half g_vh[(size_t)T_SEQ * 1024];   // V hi
__device__ __align__(16) __half g_vl[(size_t)T_SEQ * 1024];

// ---------------------------------------------------------------------------
// helpers
// ---------------------------------------------------------------------------
__device__ __forceinline__ uint32_t smem_u32(const void* p) {
  uint32_t a;
  asm("{ .reg .u64 t; cvta.to.shared.u64 t, %1; cvt.u32.u64 %0, t; }"
      : "=r"(a) : "l"(p));
  return a;
}

__device__ __forceinline__ void cp16(uint32_t dst, const void* src) {
  asm volatile("cp.async.cg.shared.global [%0], [%1], 16;"
               :: "r"(dst), "l"(src) : "memory");
}

__device__ __forceinline__ void ldsm4(unsigned r[4], uint32_t addr) {
  asm volatile("ldmatrix.sync.aligned.m8n8.x4.shared.b16 {%0,%1,%2,%3}, [%4];"
               : "=r"(r[0]), "=r"(r[1]), "=r"(r[2]), "=r"(r[3]) : "r"(addr));
}

__device__ __forceinline__ void ldsm4t(unsigned r[4], uint32_t addr) {
  asm volatile("ldmatrix.sync.aligned.m8n8.x4.trans.shared.b16 {%0,%1,%2,%3}, [%4];"
               : "=r"(r[0]), "=r"(r[1]), "=r"(r[2]), "=r"(r[3]) : "r"(addr));
}

__device__ __forceinline__ void mma_f16(float d[4], const unsigned a[4],
                                        unsigned b0, unsigned b1) {
  asm volatile(
      "mma.sync.aligned.m16n8k16.row.col.f32.f16.f16.f32 "
      "{%0,%1,%2,%3}, {%4,%5,%6,%7}, {%8,%9}, {%0,%1,%2,%3};"
      : "+f"(d[0]), "+f"(d[1]), "+f"(d[2]), "+f"(d[3])
      : "r"(a[0]), "r"(a[1]), "r"(a[2]), "r"(a[3]), "r"(b0), "r"(b1));
}

__device__ __forceinline__ void split_store(__half* H, __half* L, size_t idx,
                                            float v) {
  __half h = __float2half_rn(v);
  H[idx] = h;
  L[idx] = __float2half_rn(v - __half2float(h));
}

// ---------------------------------------------------------------------------
// Prep kernels
// ---------------------------------------------------------------------------
__global__ void split_h(const float4* __restrict__ X, uint2* __restrict__ Xh,
                        uint2* __restrict__ Xl, int n4) {
  int i = blockIdx.x * 256 + threadIdx.x;
  if (i >= n4) return;
  float4 v = X[i];
  float hx = __half2float(__float2half_rn(v.x));
  float hy = __half2float(__float2half_rn(v.y));
  float hz = __half2float(__float2half_rn(v.z));
  float hw = __half2float(__float2half_rn(v.w));
  __half2 h0 = __floats2half2_rn(hx, hy), h1 = __floats2half2_rn(hz, hw);
  __half2 l0 = __floats2half2_rn(v.x - hx, v.y - hy);
  __half2 l1 = __floats2half2_rn(v.z - hz, v.w - hw);
  uint2 ho, lo;
  ho.x = *(unsigned*)&h0; ho.y = *(unsigned*)&h1;
  lo.x = *(unsigned*)&l0; lo.y = *(unsigned*)&l1;
  Xh[i] = ho;
  Xl[i] = lo;
}

__global__ void transpose_h(const float* __restrict__ W, __half* __restrict__ Wh,
                            int K, int N) {
  __shared__ float t[32][33];
  const int n0 = blockIdx.x << 5, k0 = blockIdx.y << 5;
  const int tx = threadIdx.x, ty = threadIdx.y;  // 32 x 8
#pragma unroll
  for (int i = 0; i < 32; i += 8)
    t[ty + i][tx] = W[(size_t)(k0 + ty + i) * N + n0 + tx];
  __syncthreads();
#pragma unroll
  for (int i = 0; i < 32; i += 8)
    Wh[(size_t)(n0 + ty + i) * K + k0 + tx] = __float2half_rn(t[tx][ty + i]);
}

// Fused RoPE + fp16 hi/lo conversion
__global__ void rope_convert(const float* __restrict__ qkv,
                             const int* __restrict__ positions) {
  const int t = blockIdx.x;
  const int tid = threadIdx.x;  // 256
  const float pos = (float)positions[t];
  const float* row = qkv + (size_t)t * QKV_N;

  for (int i = tid; i < 2048; i += 256) {
    int head = i >> 6, d = i & 63;
    float inv = expf(-((float)d * (1.0f / 64.0f)) * 13.815510557964274f);
    float fr = pos * inv;
    float c = cosf(fr), s = sinf(fr);
    float x1 = row[head * 128 + d], x2 = row[head * 128 + d + 64];
    size_t o = (size_t)t * 4096 + head * 128 + d;
    split_store(g_qh, g_ql, o,      (x1 * c - x2 * s) * ATTN_SCALE);
    split_store(g_qh, g_ql, o + 64, (x2 * c + x1 * s) * ATTN_SCALE);
  }
  for (int i = tid; i < 512; i += 256) {
    int head = i >> 6, d = i & 63;
    float inv = expf(-((float)d * (1.0f / 64.0f)) * 13.815510557964274f);
    float fr = pos * inv;
    float c = cosf(fr), s = sinf(fr);
    float x1 = row[4096 + head * 128 + d], x2 = row[4096 + head * 128 + d + 64];
    size_t o = (size_t)t * 1024 + head * 128 + d;
    split_store(g_kh, g_kl, o,      x1 * c - x2 * s);
    split_store(g_kh, g_kl, o + 64, x2 * c + x1 * s);
  }
  for (int i = tid; i < 1024; i += 256)
    split_store(g_vh, g_vl, (size_t)t * 1024 + i, row[5120 + i]);
}

// ---------------------------------------------------------------------------
// 2-term fp16 GEMM, BK=64, 2-stage cp.async, 2 CTAs/SM, two-pass MMA schedule.
// Tiles: 128 rows x 128B, swizzle seg^(row&7) (8 segs of 16B per row).
// 256 threads = 8 warps (4M x 2N), warp tile 32x64.
// ---------------------------------------------------------------------------
__global__ __launch_bounds__(256, 2) void gemm_h2(
    const __half* __restrict__ pAh, const __half* __restrict__ pAl,
    const __half* __restrict__ pBh, float* __restrict__ C, int N, int K) {
  const uint32_t smb = smem_u32(dyn_smem);

  const int tid  = threadIdx.x;
  const int lane = tid & 31;
  const int warp = tid >> 5;
  const int wm = warp & 3;
  const int wn = warp >> 2;
  const int bm = blockIdx.y * 128;
  const int bn = blockIdx.x * 128;

  const __half* aH = pAh + (size_t)bm * K;
  const __half* aL = pAl + (size_t)bm * K;
  const __half* bH = pBh + (size_t)bn * K;

  // cp.async mapping: 2 threads per row, 4 consecutive 16B segs each
  const int crow = tid >> 1;
  const int csh  = (tid & 1) * 4;        // first seg index (0 or 4)
  const int crx  = crow & 7;
  const uint32_t cdr = (uint32_t)(crow * 128);

  // ldmatrix geometry (rows 128B, seg = kst*2 + halfcol, xor row&7)
  const int rowA = wm * 32 + (lane & 7) + ((lane >> 3) & 1) * 8;
  const int rxA  = lane & 7;
  const int hcA  = (lane >> 4) & 1;
  const uint32_t aofs = (uint32_t)(rowA * 128);

  const int rowB = wn * 64 + (lane & 7) + ((lane >> 4) & 1) * 8;
  const int hcB  = (lane >> 3) & 1;
  const uint32_t bofs = (uint32_t)(rowB * 128);

  float acc[2][8][4];
#pragma unroll
  for (int i = 0; i < 2; i++)
#pragma unroll
    for (int j = 0; j < 8; j++)
#pragma unroll
      for (int r = 0; r < 4; r++) acc[i][j][r] = 0.f;

  const int NC = K >> 6;  // BK=64 chunks

#define ISSUE(c)                                                              \
  do {                                                                        \
    uint32_t sb = smb + (uint32_t)((c) & 1) * GSTG;                           \
    size_t gg = (size_t)crow * K + ((c) << 6) + csh * 8;                      \
    _Pragma("unroll")                                                         \
    for (int s = 0; s < 4; ++s) {                                             \
      uint32_t d = sb + cdr + (uint32_t)(((csh + s) ^ crx) << 4);             \
      cp16(d,             aH + gg + s * 8);                                   \
      cp16(d + GTILE,     aL + gg + s * 8);                                   \
      cp16(d + 2 * GTILE, bH + gg + s * 8);                                   \
    }                                                                         \
    asm volatile("cp.async.commit_group;" ::: "memory");                      \
  } while (0)

  ISSUE(0);

  for (int c = 0; c < NC; ++c) {
    asm volatile("cp.async.wait_group 0;" ::: "memory");
    __syncthreads();
    if (c + 1 < NC) ISSUE(c + 1);

    const uint32_t sb  = smb + (uint32_t)(c & 1) * GSTG;
    const uint32_t abh = sb + aofs;
    const uint32_t bbh = sb + 2 * GTILE + bofs;

#pragma unroll
    for (int kst = 0; kst < 4; ++kst) {
      const uint32_t xa = (uint32_t)(((kst * 2 + hcA) ^ rxA) << 4);
      const uint32_t xb = (uint32_t)(((kst * 2 + hcB) ^ rxA) << 4);
      unsigned af[2][4], bf[4][4];
      // pass 1: A-hi x B (16 MMAs, distinct accumulators)
      ldsm4(af[0], abh + xa);
      ldsm4(af[1], abh + 2048 + xa);   // +16 rows
#pragma unroll
      for (int p = 0; p < 4; ++p) ldsm4(bf[p], bbh + p * 2048 + xb);
#pragma unroll
      for (int p = 0; p < 4; ++p)
#pragma unroll
        for (int mi = 0; mi < 2; ++mi)
#pragma unroll
          for (int sub = 0; sub < 2; ++sub)
            mma_f16(acc[mi][p * 2 + sub], af[mi], bf[p][sub * 2],
                    bf[p][sub * 2 + 1]);
      // pass 2: A-lo x B (reuse af regs)
      ldsm4(af[0], abh + GTILE + xa);
      ldsm4(af[1], abh + GTILE + 2048 + xa);
#pragma unroll
      for (int p = 0; p < 4; ++p)
#pragma unroll
        for (int mi = 0; mi < 2; ++mi)
#pragma unroll
          for (int sub = 0; sub < 2; ++sub)
            mma_f16(acc[mi][p * 2 + sub], af[mi], bf[p][sub * 2],
                    bf[p][sub * 2 + 1]);
    }
  }
#undef ISSUE

  const int g  = lane >> 2;
  const int tg = lane & 3;
#pragma unroll
  for (int mi = 0; mi < 2; mi++) {
    int r0 = bm + wm * 32 + mi * 16 + g;
#pragma unroll
    for (int ni = 0; ni < 8; ni++) {
      int c = bn + wn * 64 + ni * 8 + tg * 2;
      C[(size_t)r0 * N + c]           = acc[mi][ni][0];
      C[(size_t)r0 * N + c + 1]       = acc[mi][ni][1];
      C[(size_t)(r0 + 8) * N + c]     = acc[mi][ni][2];
      C[(size_t)(r0 + 8) * N + c + 1] = acc[mi][ni][3];
    }
  }
}

// ---------------------------------------------------------------------------
// Flash attention v3 (proven round-9): 128-row Q tiles, 8 warps,
// double-buffered KV, fp16 + ldmatrix.
// ---------------------------------------------------------------------------
__global__ __launch_bounds__(256) void attn3(__half* __restrict__ oh,
                                             __half* __restrict__ ol) {
  char* smc = dyn_smem;
  const uint32_t smb = smem_u32(smc);

  const int h = blockIdx.x, qt = blockIdx.y;
  const int kvh = h >> 2;
  const int q0 = qt * 128;
  const int jmax = 2 * qt + 1;
  const int tid = threadIdx.x, lane = tid & 31, w = tid >> 5;
  const int g = lane >> 2, tg = lane & 3;

  // ---- Q tile load (once): 128 rows x 128 cols, hi+lo ----
  {
    const int row = tid >> 1, s0 = (tid & 1) * 8, rx = row & 7;
    const size_t gq = (size_t)(q0 + row) * 4096 + h * 128 + s0 * 8;
    const uint32_t dr = smb + row * 256;
#pragma unroll
    for (int s = 0; s < 8; ++s) {
      uint32_t d = dr + (((s0 + s) ^ rx) << 4);
      cp16(AQH + d, g_qh + gq + s * 8);
      cp16(AQL + d, g_ql + gq + s * 8);
    }
    asm volatile("cp.async.commit_group;" ::: "memory");
  }

  const int kvrow = tid >> 2, kvs0 = (tid & 3) * 4, kvrx = kvrow & 7;

#define KV_ISSUE(j, stg)                                                      \
  do {                                                                        \
    const uint32_t base = smb + AKV + (uint32_t)(stg) * 65536;                \
    const size_t gk = (size_t)((j) * 64 + kvrow) * 1024 + kvh * 128 + kvs0 * 8; \
    _Pragma("unroll")                                                         \
    for (int s = 0; s < 4; ++s) {                                             \
      uint32_t d = (uint32_t)(kvrow * 256 + (((kvs0 + s) ^ kvrx) << 4));      \
      cp16(base + d,         g_kh + gk + s * 8);                              \
      cp16(base + 16384 + d, g_kl + gk + s * 8);                              \
      cp16(base + 32768 + d, g_vh + gk + s * 8);                              \
      cp16(base + 49152 + d, g_vl + gk + s * 8);                              \
    }                                                                         \
    asm volatile("cp.async.commit_group;" ::: "memory");                      \
  } while (0)

  KV_ISSUE(0, 0);

  const int rowA = w * 16 + (lane & 7) + ((lane >> 3) & 1) * 8;
  const int rxA = lane & 7;
  const int hcA = (lane >> 4) & 1;
  const uint32_t aQ = smb + (uint32_t)rowA * 256;
  const uint32_t aP = smb + APS + (uint32_t)rowA * 128;
  const int rBb = (lane & 7) + ((lane >> 4) & 1) * 8;
  const int hcB = (lane >> 3) & 1;
  const int subm = lane >> 3;
  const int rV = (lane & 7) + ((subm & 1) << 3);
  const int hsV = subm >> 1;

  float m0 = -1e30f, m1 = -1e30f, l0 = 0.f, l1 = 0.f;
  float O[16][4];
#pragma unroll
  for (int i = 0; i < 16; i++)
#pragma unroll
    for (int r = 0; r < 4; r++) O[i][r] = 0.f;

  for (int j = 0; j <= jmax; ++j) {
    __syncthreads();
    if (j < jmax) {
      KV_ISSUE(j + 1, (j + 1) & 1);
      asm volatile("cp.async.wait_group 1;" ::: "memory");
    } else {
      asm volatile("cp.async.wait_group 0;" ::: "memory");
    }
    __syncthreads();

    const uint32_t kvb = smb + AKV + (uint32_t)(j & 1) * 65536;

    // ---- S = Qs K^T, 3-term fp16 ----
    float s[8][4];
#pragma unroll
    for (int ni = 0; ni < 8; ni++)
#pragma unroll
      for (int r = 0; r < 4; r++) s[ni][r] = 0.f;

#pragma unroll
    for (int kst = 0; kst < 8; ++kst) {
      unsigned qh[4], ql[4];
      const uint32_t xa = (uint32_t)(((kst * 2 + hcA) ^ rxA) << 4);
      ldsm4(qh, aQ + AQH + xa);
      ldsm4(ql, aQ + AQL + xa);
#pragma unroll
      for (int p = 0; p < 4; ++p) {
        const int rb = p * 16 + rBb;
        const uint32_t ab =
            kvb + (uint32_t)rb * 256 + (uint32_t)(((kst * 2 + hcB) ^ (rb & 7)) << 4);
        unsigned kh[4], kl[4];
        ldsm4(kh, ab);
        ldsm4(kl, ab + 16384);
        const int n0i = p * 2;
        mma_f16(s[n0i],     qh, kh[0], kh[1]);
        mma_f16(s[n0i + 1], qh, kh[2], kh[3]);
        mma_f16(s[n0i],     ql, kh[0], kh[1]);
        mma_f16(s[n0i + 1], ql, kh[2], kh[3]);
        mma_f16(s[n0i],     qh, kl[0], kl[1]);
        mma_f16(s[n0i + 1], qh, kl[2], kl[3]);
      }
    }

    // ---- online softmax ----
    const int gr0 = q0 + w * 16 + g;
    const int gr1 = gr0 + 8;
    float tm0 = -1e30f, tm1 = -1e30f;
#pragma unroll
    for (int ni = 0; ni < 8; ni++) {
#pragma unroll
      for (int cc = 0; cc < 2; cc++) {
        int gc = j * 64 + ni * 8 + tg * 2 + cc;
        float v0 = s[ni][cc];
        float v1 = s[ni][2 + cc];
        if (gc > gr0) v0 = -1e30f;
        if (gc > gr1) v1 = -1e30f;
        s[ni][cc] = v0;
        s[ni][2 + cc] = v1;
        tm0 = fmaxf(tm0, v0);
        tm1 = fmaxf(tm1, v1);
      }
    }
    tm0 = fmaxf(tm0, __shfl_xor_sync(0xffffffffu, tm0, 1));
    tm0 = fmaxf(tm0, __shfl_xor_sync(0xffffffffu, tm0, 2));
    tm1 = fmaxf(tm1, __shfl_xor_sync(0xffffffffu, tm1, 1));
    tm1 = fmaxf(tm1, __shfl_xor_sync(0xffffffffu, tm1, 2));

    float nm0 = fmaxf(m0, tm0), nm1 = fmaxf(m1, tm1);
    float a0 = __expf(m0 - nm0), a1 = __expf(m1 - nm1);

    const uint32_t pr0 = APS + (uint32_t)(w * 16 + g) * 128;
    const uint32_t pr1 = pr0 + 1024;
    float ps0 = 0.f, ps1 = 0.f;
#pragma unroll
    for (int ni = 0; ni < 8; ni++) {
      float p00 = __expf(s[ni][0] - nm0);
      float p01 = __expf(s[ni][1] - nm0);
      float p10 = __expf(s[ni][2] - nm1);
      float p11 = __expf(s[ni][3] - nm1);
      ps0 += p00 + p01;
      ps1 += p10 + p11;
      const uint32_t px = (uint32_t)(((ni ^ g) << 4) + tg * 4);
      *reinterpret_cast<__half2*>(smc + pr0 + px) = __floats2half2_rn(p00, p01);
      *reinterpret_cast<__half2*>(smc + pr1 + px) = __floats2half2_rn(p10, p11);
    }
    ps0 += __shfl_xor_sync(0xffffffffu, ps0, 1);
    ps0 += __shfl_xor_sync(0xffffffffu, ps0, 2);
    ps1 += __shfl_xor_sync(0xffffffffu, ps1, 1);
    ps1 += __shfl_xor_sync(0xffffffffu, ps1, 2);

    l0 = l0 * a0 + ps0;
    l1 = l1 * a1 + ps1;
    m0 = nm0;
    m1 = nm1;
#pragma unroll
    for (int ni = 0; ni < 16; ni++) {
      O[ni][0] *= a0; O[ni][1] *= a0;
      O[ni][2] *= a1; O[ni][3] *= a1;
    }
    __syncwarp();

    // ---- O += P (Vh + Vl), two passes ----
#pragma unroll
    for (int k2 = 0; k2 < 4; ++k2) {
      unsigned pf[4];
      ldsm4(pf, aP + (uint32_t)(((k2 * 2 + hcA) ^ rxA) << 4));
      const int rv = k2 * 16 + rV;
      const uint32_t vb = kvb + 32768 + (uint32_t)rv * 256;
      const int rxv = rv & 7;
      unsigned vf[8][4];
#pragma unroll
      for (int dg = 0; dg < 8; ++dg)
        ldsm4t(vf[dg], vb + (uint32_t)(((dg * 2 + hsV) ^ rxv) << 4));
#pragma unroll
      for (int dg = 0; dg < 8; ++dg) {
        mma_f16(O[dg * 2],     pf, vf[dg][0], vf[dg][1]);
        mma_f16(O[dg * 2 + 1], pf, vf[dg][2], vf[dg][3]);
      }
#pragma unroll
      for (int dg = 0; dg < 8; ++dg)
        ldsm4t(vf[dg], vb + 16384 + (uint32_t)(((dg * 2 + hsV) ^ rxv) << 4));
#pragma unroll
      for (int dg = 0; dg < 8; ++dg) {
        mma_f16(O[dg * 2],     pf, vf[dg][0], vf[dg][1]);
        mma_f16(O[dg * 2 + 1], pf, vf[dg][2], vf[dg][3]);
      }
    }
  }
#undef KV_ISSUE

  // epilogue -> fp16 hi/lo, half2 paired stores
  const float inv0 = 1.f / l0;
  const float inv1 = 1.f / l1;
  const int r0 = q0 + w * 16 + g;
#pragma unroll
  for (int ni = 0; ni < 16; ni++) {
    const int c = h * HD + ni * 8 + tg * 2;
    const size_t i0 = (size_t)r0 * HID + c;
    const size_t i1 = (size_t)(r0 + 8) * HID + c;
    float v00 = O[ni][0] * inv0, v01 = O[ni][1] * inv0;
    float v10 = O[ni][2] * inv1, v11 = O[ni][3] * inv1;
    __half2 h0 = __floats2half2_rn(v00, v01);
    __half2 h1 = __floats2half2_rn(v10, v11);
    *reinterpret_cast<__half2*>(oh + i0) = h0;
    *reinterpret_cast<__half2*>(oh + i1) = h1;
    *reinterpret_cast<__half2*>(ol + i0) =
        __floats2half2_rn(v00 - __half2float(__low2half(h0)),
                          v01 - __half2float(__high2half(h0)));
    *reinterpret_cast<__half2*>(ol + i1) =
        __floats2half2_rn(v10 - __half2float(__low2half(h1)),
                          v11 - __half2float(__high2half(h1)));
  }
}

// ---------------------------------------------------------------------------
// launch
// ---------------------------------------------------------------------------
extern "C" void kernel_launch(void* const* d_in, const int* in_sizes, int n_in,
                              void* d_out, int out_size) {
  (void)in_sizes; (void)n_in; (void)out_size;
  const int*   positions = (const int*)d_in[0];
  const float* hidden    = (const float*)d_in[1];
  const float* Wqkv      = (const float*)d_in[2];
  const float* Wo        = (const float*)d_in[3];
  float* out = (float*)d_out;

  float* qkv_p;
  __half *ah, *al, *wqh, *woh;
  cudaGetSymbolAddress((void**)&qkv_p, g_qkv);
  cudaGetSymbolAddress((void**)&ah, g_ah);
  cudaGetSymbolAddress((void**)&al, g_al);
  cudaGetSymbolAddress((void**)&wqh, g_wqh);
  cudaGetSymbolAddress((void**)&woh, g_woh);

  cudaFuncSetAttribute(gemm_h2, cudaFuncAttributeMaxDynamicSharedMemorySize,
                       GEMM_SMEM);
  cudaFuncSetAttribute(attn3, cudaFuncAttributeMaxDynamicSharedMemorySize,
                       ATTN_SMEM);

  // Prep
  transpose_h<<<dim3(QKV_N / 32, HID / 32), dim3(32, 8)>>>(Wqkv, wqh, HID, QKV_N);
  transpose_h<<<dim3(HID / 32, HID / 32), dim3(32, 8)>>>(Wo, woh, HID, HID);
  split_h<<<(T_SEQ * HID / 4 + 255) / 256, 256>>>(
      (const float4*)hidden, (uint2*)ah, (uint2*)al, T_SEQ * HID / 4);

  // 1) QKV projection
  gemm_h2<<<dim3(QKV_N / 128, T_SEQ / 128), 256, GEMM_SMEM>>>(
      ah, al, wqh, qkv_p, QKV_N, HID);
  // 2) RoPE + fp16 conversion
  rope_convert<<<T_SEQ, 256>>>(qkv_p, positions);
  // 3) Flash attention (writes fp16 hi/lo into g_ah/g_al)
  attn3<<<dim3(NHEADS, T_SEQ / 128), 256, ATTN_SMEM>>>(ah, al);
  // 4) Output projection
  gemm_h2<<<dim3(HID / 128, T_SEQ / 128), 256, GEMM_SMEM>>>(
      ah, al, woh, out, HID, HID);
}

// round 12
// speedup vs baseline: 1.4527x; 1.4527x over previous
#include <cuda_runtime.h>
#include <cuda_fp16.h>
#include <cstdint>

#define T_SEQ 2048
#define HID   4096
#define QKV_N 6144
#define HD    128
#define NHEADS 32
#define ATTN_SCALE 0.08838834764831845f   // 128^-0.5

// GEMM: BM=BN=128, BK=32 (fp16), 2 tiles/stage (A,B) 8KB each, 4 stages,
// 2 CTAs/SM.  (structure = round-8 proven config minus the A-lo tile)
#define GT 8192
#define GSTG (2 * GT)
#define GEMM_SMEM (4 * GSTG)   // 64KB

// Attention v3: Q 128x128 hi/lo (64KB) + 2-stage KV (2x64KB) + P 128x64 (16KB)
#define AQH 0
#define AQL 32768
#define AKV 65536          // stage s at AKV + s*65536: Kh,Kl,Vh,Vl 16KB each
#define APS (AKV + 2 * 65536)
#define ATTN_SMEM (APS + 16384)   // 212992

extern __shared__ char dyn_smem[];

// ---------------------------------------------------------------------------
// Scratch (allocation-free rule: __device__ globals)
// ---------------------------------------------------------------------------
__device__ float g_qkv[(size_t)T_SEQ * QKV_N];
__device__ __align__(16) __half g_ah[(size_t)T_SEQ * HID];    // GEMM A (fp16)
__device__ __align__(16) __half g_wqh[(size_t)QKV_N * HID];   // Wqkv^T fp16 [N,K]
__device__ __align__(16) __half g_woh[(size_t)HID * HID];     // Wo^T fp16
__device__ __align__(16) __half g_qh[(size_t)T_SEQ * HID];    // roped+scaled Q hi
__device__ __align__(16) __half g_ql[(size_t)T_SEQ * HID];
__device__ __align__(16) __half g_kh[(size_t)T_SEQ * 1024];   // roped K hi
__device__ __align__(16) __half g_kl[(size_t)T_SEQ * 1024];
__device__ __align__(16) __half g_vh[(size_t)T_SEQ * 1024];   // V hi
__device__ __align__(16) __half g_vl[(size_t)T_SEQ * 1024];

// ---------------------------------------------------------------------------
// helpers
// ---------------------------------------------------------------------------
__device__ __forceinline__ uint32_t smem_u32(const void* p) {
  uint32_t a;
  asm("{ .reg .u64 t; cvta.to.shared.u64 t, %1; cvt.u32.u64 %0, t; }"
      : "=r"(a) : "l"(p));
  return a;
}

__device__ __forceinline__ void cp16(uint32_t dst, const void* src) {
  asm volatile("cp.async.cg.shared.global [%0], [%1], 16;"
               :: "r"(dst), "l"(src) : "memory");
}

__device__ __forceinline__ void ldsm4(unsigned r[4], uint32_t addr) {
  asm volatile("ldmatrix.sync.aligned.m8n8.x4.shared.b16 {%0,%1,%2,%3}, [%4];"
               : "=r"(r[0]), "=r"(r[1]), "=r"(r[2]), "=r"(r[3]) : "r"(addr));
}

__device__ __forceinline__ void ldsm4t(unsigned r[4], uint32_t addr) {
  asm volatile("ldmatrix.sync.aligned.m8n8.x4.trans.shared.b16 {%0,%1,%2,%3}, [%4];"
               : "=r"(r[0]), "=r"(r[1]), "=r"(r[2]), "=r"(r[3]) : "r"(addr));
}

__device__ __forceinline__ void mma_f16(float d[4], const unsigned a[4],
                                        unsigned b0, unsigned b1) {
  asm volatile(
      "mma.sync.aligned.m16n8k16.row.col.f32.f16.f16.f32 "
      "{%0,%1,%2,%3}, {%4,%5,%6,%7}, {%8,%9}, {%0,%1,%2,%3};"
      : "+f"(d[0]), "+f"(d[1]), "+f"(d[2]), "+f"(d[3])
      : "r"(a[0]), "r"(a[1]), "r"(a[2]), "r"(a[3]), "r"(b0), "r"(b1));
}

__device__ __forceinline__ void split_store(__half* H, __half* L, size_t idx,
                                            float v) {
  __half h = __float2half_rn(v);
  H[idx] = h;
  L[idx] = __float2half_rn(v - __half2float(h));
}

// ---------------------------------------------------------------------------
// Prep kernels
// ---------------------------------------------------------------------------
// fp32 -> fp16 (GEMM activations, 1-term)
__global__ void conv_h(const float4* __restrict__ X, uint2* __restrict__ Xh,
                       int n4) {
  int i = blockIdx.x * 256 + threadIdx.x;
  if (i >= n4) return;
  float4 v = X[i];
  __half2 h0 = __floats2half2_rn(v.x, v.y), h1 = __floats2half2_rn(v.z, v.w);
  uint2 ho;
  ho.x = *(unsigned*)&h0; ho.y = *(unsigned*)&h1;
  Xh[i] = ho;
}

__global__ void transpose_h(const float* __restrict__ W, __half* __restrict__ Wh,
                            int K, int N) {
  __shared__ float t[32][33];
  const int n0 = blockIdx.x << 5, k0 = blockIdx.y << 5;
  const int tx = threadIdx.x, ty = threadIdx.y;  // 32 x 8
#pragma unroll
  for (int i = 0; i < 32; i += 8)
    t[ty + i][tx] = W[(size_t)(k0 + ty + i) * N + n0 + tx];
  __syncthreads();
#pragma unroll
  for (int i = 0; i < 32; i += 8)
    Wh[(size_t)(n0 + ty + i) * K + k0 + tx] = __float2half_rn(t[tx][ty + i]);
}

// Fused RoPE + fp16 hi/lo conversion (attention keeps its proven precision)
__global__ void rope_convert(const float* __restrict__ qkv,
                             const int* __restrict__ positions) {
  const int t = blockIdx.x;
  const int tid = threadIdx.x;  // 256
  const float pos = (float)positions[t];
  const float* row = qkv + (size_t)t * QKV_N;

  for (int i = tid; i < 2048; i += 256) {
    int head = i >> 6, d = i & 63;
    float inv = expf(-((float)d * (1.0f / 64.0f)) * 13.815510557964274f);
    float fr = pos * inv;
    float c = cosf(fr), s = sinf(fr);
    float x1 = row[head * 128 + d], x2 = row[head * 128 + d + 64];
    size_t o = (size_t)t * 4096 + head * 128 + d;
    split_store(g_qh, g_ql, o,      (x1 * c - x2 * s) * ATTN_SCALE);
    split_store(g_qh, g_ql, o + 64, (x2 * c + x1 * s) * ATTN_SCALE);
  }
  for (int i = tid; i < 512; i += 256) {
    int head = i >> 6, d = i & 63;
    float inv = expf(-((float)d * (1.0f / 64.0f)) * 13.815510557964274f);
    float fr = pos * inv;
    float c = cosf(fr), s = sinf(fr);
    float x1 = row[4096 + head * 128 + d], x2 = row[4096 + head * 128 + d + 64];
    size_t o = (size_t)t * 1024 + head * 128 + d;
    split_store(g_kh, g_kl, o,      x1 * c - x2 * s);
    split_store(g_kh, g_kl, o + 64, x2 * c + x1 * s);
  }
  for (int i = tid; i < 1024; i += 256)
    split_store(g_vh, g_vl, (size_t)t * 1024 + i, row[5120 + i]);
}

// ---------------------------------------------------------------------------
// 1-term fp16 GEMM: C = fp16(A) @ fp16(B)^T.  A [M,K], B [N,K] fp16.
// Round-8 proven structure: BK=32, 4-stage cp.async (wait_group 2),
// 2 CTAs/SM, 8 warps (4Mx2N), warp tile 32x64, 16 distinct-acc MMAs/kst.
// smem tile 128 rows x 64B, swizzle seg^((row>>1)&3).
// ---------------------------------------------------------------------------
__global__ __launch_bounds__(256, 2) void gemm_h1(
    const __half* __restrict__ pA, const __half* __restrict__ pB,
    float* __restrict__ C, int N, int K) {
  const uint32_t smb = smem_u32(dyn_smem);

  const int tid  = threadIdx.x;
  const int lane = tid & 31;
  const int warp = tid >> 5;
  const int wm = warp & 3;
  const int wn = warp >> 2;
  const int bm = blockIdx.y * 128;
  const int bn = blockIdx.x * 128;

  const __half* aP = pA + (size_t)bm * K;
  const __half* bP = pB + (size_t)bn * K;

  const int crow = tid >> 1;
  const int cs0  = (tid & 1) << 1;
  const int csw  = (crow >> 1) & 3;
  const uint32_t cd0 = (uint32_t)(crow * 64 + ((cs0 ^ csw) << 4));
  const uint32_t cd1 = (uint32_t)(crow * 64 + (((cs0 + 1) ^ csw) << 4));
  const int cse = cs0 << 3;

  const int rowA = wm * 32 + (lane & 7) + ((lane >> 3) & 1) * 8;
  const int hcA  = (lane >> 4) & 1;
  const int swA  = (rowA >> 1) & 3;
  const uint32_t aofs = (uint32_t)(rowA * 64);
  const uint32_t xsa0 = (uint32_t)(((0 * 2 + hcA) ^ swA) << 4);
  const uint32_t xsa1 = (uint32_t)(((1 * 2 + hcA) ^ swA) << 4);

  const int rowB = wn * 64 + (lane & 7) + ((lane >> 4) & 1) * 8;
  const int hcB  = (lane >> 3) & 1;
  const int swB  = (rowB >> 1) & 3;
  const uint32_t bofs = (uint32_t)(rowB * 64);
  const uint32_t xsb0 = (uint32_t)(((0 * 2 + hcB) ^ swB) << 4);
  const uint32_t xsb1 = (uint32_t)(((1 * 2 + hcB) ^ swB) << 4);

  float acc[2][8][4];
#pragma unroll
  for (int i = 0; i < 2; i++)
#pragma unroll
    for (int j = 0; j < 8; j++)
#pragma unroll
      for (int r = 0; r < 4; r++) acc[i][j][r] = 0.f;

  const int NC = K >> 5;

#define ISSUE(c)                                                              \
  do {                                                                        \
    uint32_t sb = smb + (uint32_t)((c) & 3) * GSTG;                           \
    size_t gg = (size_t)crow * K + ((c) << 5) + cse;                          \
    cp16(sb + cd0,      aP + gg); cp16(sb + cd1,      aP + gg + 8);           \
    cp16(sb + GT + cd0, bP + gg); cp16(sb + GT + cd1, bP + gg + 8);           \
    asm volatile("cp.async.commit_group;" ::: "memory");                      \
  } while (0)

  ISSUE(0);
  ISSUE(1);
  ISSUE(2);

  for (int c = 0; c < NC; ++c) {
    asm volatile("cp.async.wait_group 2;" ::: "memory");
    __syncthreads();
    if (c + 3 < NC) ISSUE(c + 3);

    const uint32_t sb  = smb + (uint32_t)(c & 3) * GSTG;
    const uint32_t ab = sb + aofs;
    const uint32_t bb = sb + GT + bofs;

#pragma unroll
    for (int st = 0; st < 2; ++st) {
      const uint32_t xa = st ? xsa1 : xsa0;
      const uint32_t xb = st ? xsb1 : xsb0;
      unsigned af[2][4], bf[4][4];
      ldsm4(af[0], ab + xa);
      ldsm4(af[1], ab + 1024 + xa);
#pragma unroll
      for (int p = 0; p < 4; ++p) ldsm4(bf[p], bb + p * 1024 + xb);
#pragma unroll
      for (int p = 0; p < 4; ++p)
#pragma unroll
        for (int mi = 0; mi < 2; ++mi)
#pragma unroll
          for (int sub = 0; sub < 2; ++sub)
            mma_f16(acc[mi][p * 2 + sub], af[mi], bf[p][sub * 2],
                    bf[p][sub * 2 + 1]);
    }
  }
#undef ISSUE

  const int g  = lane >> 2;
  const int tg = lane & 3;
#pragma unroll
  for (int mi = 0; mi < 2; mi++) {
    int r0 = bm + wm * 32 + mi * 16 + g;
#pragma unroll
    for (int ni = 0; ni < 8; ni++) {
      int c = bn + wn * 64 + ni * 8 + tg * 2;
      C[(size_t)r0 * N + c]           = acc[mi][ni][0];
      C[(size_t)r0 * N + c + 1]       = acc[mi][ni][1];
      C[(size_t)(r0 + 8) * N + c]     = acc[mi][ni][2];
      C[(size_t)(r0 + 8) * N + c + 1] = acc[mi][ni][3];
    }
  }
}

// ---------------------------------------------------------------------------
// Flash attention v3 (proven round-9): 128-row Q tiles, 8 warps,
// double-buffered KV, fp16 + ldmatrix. Epilogue now fp16-only (1-term Wo).
// ---------------------------------------------------------------------------
__global__ __launch_bounds__(256) void attn3(__half* __restrict__ oh) {
  char* smc = dyn_smem;
  const uint32_t smb = smem_u32(smc);

  const int h = blockIdx.x, qt = blockIdx.y;
  const int kvh = h >> 2;
  const int q0 = qt * 128;
  const int jmax = 2 * qt + 1;
  const int tid = threadIdx.x, lane = tid & 31, w = tid >> 5;
  const int g = lane >> 2, tg = lane & 3;

  // ---- Q tile load (once): 128 rows x 128 cols, hi+lo ----
  {
    const int row = tid >> 1, s0 = (tid & 1) * 8, rx = row & 7;
    const size_t gq = (size_t)(q0 + row) * 4096 + h * 128 + s0 * 8;
    const uint32_t dr = smb + row * 256;
#pragma unroll
    for (int s = 0; s < 8; ++s) {
      uint32_t d = dr + (((s0 + s) ^ rx) << 4);
      cp16(AQH + d, g_qh + gq + s * 8);
      cp16(AQL + d, g_ql + gq + s * 8);
    }
    asm volatile("cp.async.commit_group;" ::: "memory");
  }

  const int kvrow = tid >> 2, kvs0 = (tid & 3) * 4, kvrx = kvrow & 7;

#define KV_ISSUE(j, stg)                                                      \
  do {                                                                        \
    const uint32_t base = smb + AKV + (uint32_t)(stg) * 65536;                \
    const size_t gk = (size_t)((j) * 64 + kvrow) * 1024 + kvh * 128 + kvs0 * 8; \
    _Pragma("unroll")                                                         \
    for (int s = 0; s < 4; ++s) {                                             \
      uint32_t d = (uint32_t)(kvrow * 256 + (((kvs0 + s) ^ kvrx) << 4));      \
      cp16(base + d,         g_kh + gk + s * 8);                              \
      cp16(base + 16384 + d, g_kl + gk + s * 8);                              \
      cp16(base + 32768 + d, g_vh + gk + s * 8);                              \
      cp16(base + 49152 + d, g_vl + gk + s * 8);                              \
    }                                                                         \
    asm volatile("cp.async.commit_group;" ::: "memory");                      \
  } while (0)

  KV_ISSUE(0, 0);

  const int rowA = w * 16 + (lane & 7) + ((lane >> 3) & 1) * 8;
  const int rxA = lane & 7;
  const int hcA = (lane >> 4) & 1;
  const uint32_t aQ = smb + (uint32_t)rowA * 256;
  const uint32_t aP = smb + APS + (uint32_t)rowA * 128;
  const int rBb = (lane & 7) + ((lane >> 4) & 1) * 8;
  const int hcB = (lane >> 3) & 1;
  const int subm = lane >> 3;
  const int rV = (lane & 7) + ((subm & 1) << 3);
  const int hsV = subm >> 1;

  float m0 = -1e30f, m1 = -1e30f, l0 = 0.f, l1 = 0.f;
  float O[16][4];
#pragma unroll
  for (int i = 0; i < 16; i++)
#pragma unroll
    for (int r = 0; r < 4; r++) O[i][r] = 0.f;

  for (int j = 0; j <= jmax; ++j) {
    __syncthreads();
    if (j < jmax) {
      KV_ISSUE(j + 1, (j + 1) & 1);
      asm volatile("cp.async.wait_group 1;" ::: "memory");
    } else {
      asm volatile("cp.async.wait_group 0;" ::: "memory");
    }
    __syncthreads();

    const uint32_t kvb = smb + AKV + (uint32_t)(j & 1) * 65536;

    // ---- S = Qs K^T, 3-term fp16 ----
    float s[8][4];
#pragma unroll
    for (int ni = 0; ni < 8; ni++)
#pragma unroll
      for (int r = 0; r < 4; r++) s[ni][r] = 0.f;

#pragma unroll
    for (int kst = 0; kst < 8; ++kst) {
      unsigned qh[4], ql[4];
      const uint32_t xa = (uint32_t)(((kst * 2 + hcA) ^ rxA) << 4);
      ldsm4(qh, aQ + AQH + xa);
      ldsm4(ql, aQ + AQL + xa);
#pragma unroll
      for (int p = 0; p < 4; ++p) {
        const int rb = p * 16 + rBb;
        const uint32_t ab =
            kvb + (uint32_t)rb * 256 + (uint32_t)(((kst * 2 + hcB) ^ (rb & 7)) << 4);
        unsigned kh[4], kl[4];
        ldsm4(kh, ab);
        ldsm4(kl, ab + 16384);
        const int n0i = p * 2;
        mma_f16(s[n0i],     qh, kh[0], kh[1]);
        mma_f16(s[n0i + 1], qh, kh[2], kh[3]);
        mma_f16(s[n0i],     ql, kh[0], kh[1]);
        mma_f16(s[n0i + 1], ql, kh[2], kh[3]);
        mma_f16(s[n0i],     qh, kl[0], kl[1]);
        mma_f16(s[n0i + 1], qh, kl[2], kl[3]);
      }
    }

    // ---- online softmax ----
    const int gr0 = q0 + w * 16 + g;
    const int gr1 = gr0 + 8;
    float tm0 = -1e30f, tm1 = -1e30f;
#pragma unroll
    for (int ni = 0; ni < 8; ni++) {
#pragma unroll
      for (int cc = 0; cc < 2; cc++) {
        int gc = j * 64 + ni * 8 + tg * 2 + cc;
        float v0 = s[ni][cc];
        float v1 = s[ni][2 + cc];
        if (gc > gr0) v0 = -1e30f;
        if (gc > gr1) v1 = -1e30f;
        s[ni][cc] = v0;
        s[ni][2 + cc] = v1;
        tm0 = fmaxf(tm0, v0);
        tm1 = fmaxf(tm1, v1);
      }
    }
    tm0 = fmaxf(tm0, __shfl_xor_sync(0xffffffffu, tm0, 1));
    tm0 = fmaxf(tm0, __shfl_xor_sync(0xffffffffu, tm0, 2));
    tm1 = fmaxf(tm1, __shfl_xor_sync(0xffffffffu, tm1, 1));
    tm1 = fmaxf(tm1, __shfl_xor_sync(0xffffffffu, tm1, 2));

    float nm0 = fmaxf(m0, tm0), nm1 = fmaxf(m1, tm1);
    float a0 = __expf(m0 - nm0), a1 = __expf(m1 - nm1);

    const uint32_t pr0 = APS + (uint32_t)(w * 16 + g) * 128;
    const uint32_t pr1 = pr0 + 1024;
    float ps0 = 0.f, ps1 = 0.f;
#pragma unroll
    for (int ni = 0; ni < 8; ni++) {
      float p00 = __expf(s[ni][0] - nm0);
      float p01 = __expf(s[ni][1] - nm0);
      float p10 = __expf(s[ni][2] - nm1);
      float p11 = __expf(s[ni][3] - nm1);
      ps0 += p00 + p01;
      ps1 += p10 + p11;
      const uint32_t px = (uint32_t)(((ni ^ g) << 4) + tg * 4);
      *reinterpret_cast<__half2*>(smc + pr0 + px) = __floats2half2_rn(p00, p01);
      *reinterpret_cast<__half2*>(smc + pr1 + px) = __floats2half2_rn(p10, p11);
    }
    ps0 += __shfl_xor_sync(0xffffffffu, ps0, 1);
    ps0 += __shfl_xor_sync(0xffffffffu, ps0, 2);
    ps1 += __shfl_xor_sync(0xffffffffu, ps1, 1);
    ps1 += __shfl_xor_sync(0xffffffffu, ps1, 2);

    l0 = l0 * a0 + ps0;
    l1 = l1 * a1 + ps1;
    m0 = nm0;
    m1 = nm1;
#pragma unroll
    for (int ni = 0; ni < 16; ni++) {
      O[ni][0] *= a0; O[ni][1] *= a0;
      O[ni][2] *= a1; O[ni][3] *= a1;
    }
    __syncwarp();

    // ---- O += P (Vh + Vl), two passes ----
#pragma unroll
    for (int k2 = 0; k2 < 4; ++k2) {
      unsigned pf[4];
      ldsm4(pf, aP + (uint32_t)(((k2 * 2 + hcA) ^ rxA) << 4));
      const int rv = k2 * 16 + rV;
      const uint32_t vb = kvb + 32768 + (uint32_t)rv * 256;
      const int rxv = rv & 7;
      unsigned vf[8][4];
#pragma unroll
      for (int dg = 0; dg < 8; ++dg)
        ldsm4t(vf[dg], vb + (uint32_t)(((dg * 2 + hsV) ^ rxv) << 4));
#pragma unroll
      for (int dg = 0; dg < 8; ++dg) {
        mma_f16(O[dg * 2],     pf, vf[dg][0], vf[dg][1]);
        mma_f16(O[dg * 2 + 1], pf, vf[dg][2], vf[dg][3]);
      }
#pragma unroll
      for (int dg = 0; dg < 8; ++dg)
        ldsm4t(vf[dg], vb + 16384 + (uint32_t)(((dg * 2 + hsV) ^ rxv) << 4));
#pragma unroll
      for (int dg = 0; dg < 8; ++dg) {
        mma_f16(O[dg * 2],     pf, vf[dg][0], vf[dg][1]);
        mma_f16(O[dg * 2 + 1], pf, vf[dg][2], vf[dg][3]);
      }
    }
  }
#undef KV_ISSUE

  // epilogue -> fp16 (feeds 1-term Wo GEMM)
  const float inv0 = 1.f / l0;
  const float inv1 = 1.f / l1;
  const int r0 = q0 + w * 16 + g;
#pragma unroll
  for (int ni = 0; ni < 16; ni++) {
    const int c = h * HD + ni * 8 + tg * 2;
    const size_t i0 = (size_t)r0 * HID + c;
    const size_t i1 = (size_t)(r0 + 8) * HID + c;
    *reinterpret_cast<__half2*>(oh + i0) =
        __floats2half2_rn(O[ni][0] * inv0, O[ni][1] * inv0);
    *reinterpret_cast<__half2*>(oh + i1) =
        __floats2half2_rn(O[ni][2] * inv1, O[ni][3] * inv1);
  }
}

// ---------------------------------------------------------------------------
// launch
// ---------------------------------------------------------------------------
extern "C" void kernel_launch(void* const* d_in, const int* in_sizes, int n_in,
                              void* d_out, int out_size) {
  (void)in_sizes; (void)n_in; (void)out_size;
  const int*   positions = (const int*)d_in[0];
  const float* hidden    = (const float*)d_in[1];
  const float* Wqkv      = (const float*)d_in[2];
  const float* Wo        = (const float*)d_in[3];
  float* out = (float*)d_out;

  float* qkv_p;
  __half *ah, *wqh, *woh;
  cudaGetSymbolAddress((void**)&qkv_p, g_qkv);
  cudaGetSymbolAddress((void**)&ah, g_ah);
  cudaGetSymbolAddress((void**)&wqh, g_wqh);
  cudaGetSymbolAddress((void**)&woh, g_woh);

  cudaFuncSetAttribute(gemm_h1, cudaFuncAttributeMaxDynamicSharedMemorySize,
                       GEMM_SMEM);
  cudaFuncSetAttribute(attn3, cudaFuncAttributeMaxDynamicSharedMemorySize,
                       ATTN_SMEM);

  // Prep
  transpose_h<<<dim3(QKV_N / 32, HID / 32), dim3(32, 8)>>>(Wqkv, wqh, HID, QKV_N);
  transpose_h<<<dim3(HID / 32, HID / 32), dim3(32, 8)>>>(Wo, woh, HID, HID);
  conv_h<<<(T_SEQ * HID / 4 + 255) / 256, 256>>>(
      (const float4*)hidden, (uint2*)ah, T_SEQ * HID / 4);

  // 1) QKV projection (1-term fp16)
  gemm_h1<<<dim3(QKV_N / 128, T_SEQ / 128), 256, GEMM_SMEM>>>(
      ah, wqh, qkv_p, QKV_N, HID);
  // 2) RoPE + fp16 conversion (attention keeps hi/lo precision)
  rope_convert<<<T_SEQ, 256>>>(qkv_p, positions);
  // 3) Flash attention (writes fp16 into g_ah)
  attn3<<<dim3(NHEADS, T_SEQ / 128), 256, ATTN_SMEM>>>(ah);
  // 4) Output projection (1-term fp16)
  gemm_h1<<<dim3(HID / 128, T_SEQ / 128), 256, GEMM_SMEM>>>(
      ah, woh, out, HID, HID);
}

// round 13
// speedup vs baseline: 1.6446x; 1.1321x over previous
#include <cuda_runtime.h>
#include <cuda_fp16.h>
#include <cstdint>

#define T_SEQ 2048
#define HID   4096
#define QKV_N 6144
#define HD    128
#define NHEADS 32
#define ATTN_SCALE 0.08838834764831845f   // 128^-0.5

// GEMM: BM=BN=128, BK=32 (fp16). A tile 128x64B (8KB), B tile 32x256B (8KB,
// [K,N] layout, trans-ldmatrix). 4 stages, 2 CTAs/SM.
#define GT 8192
#define GSTG 16384
#define GEMM_SMEM (4 * GSTG)   // 64KB

// Attention: Q 128x128 hi/lo (64KB) + 2-stage KV (Kh,Kl,Vh 48KB each) + P 16KB
#define AQH 0
#define AQL 32768
#define AKV 65536
#define AKVS 49152
#define APS (AKV + 2 * AKVS)      // 163840
#define ATTN_SMEM (APS + 16384)   // 180224

extern __shared__ char dyn_smem[];

// ---------------------------------------------------------------------------
// Scratch (allocation-free rule: __device__ globals)
// ---------------------------------------------------------------------------
__device__ float g_qkv[(size_t)T_SEQ * QKV_N];
__device__ __align__(16) __half g_ah[(size_t)T_SEQ * HID];    // GEMM A (fp16)
__device__ __align__(16) __half g_wq16[(size_t)HID * QKV_N];  // Wqkv fp16 [K,N]
__device__ __align__(16) __half g_wo16[(size_t)HID * HID];    // Wo fp16 [K,N]
__device__ __align__(16) __half g_qh[(size_t)T_SEQ * HID];    // roped+scaled Q hi
__device__ __align__(16) __half g_ql[(size_t)T_SEQ * HID];
__device__ __align__(16) __half g_kh[(size_t)T_SEQ * 1024];   // roped K hi
__device__ __align__(16) __half g_kl[(size_t)T_SEQ * 1024];
__device__ __align__(16) __half g_vh[(size_t)T_SEQ * 1024];   // V (fp16)
__device__ __align__(8) float2 g_rope[(size_t)T_SEQ * 64];    // cos/sin table

// ---------------------------------------------------------------------------
// helpers
// ---------------------------------------------------------------------------
__device__ __forceinline__ uint32_t smem_u32(const void* p) {
  uint32_t a;
  asm("{ .reg .u64 t; cvta.to.shared.u64 t, %1; cvt.u32.u64 %0, t; }"
      : "=r"(a) : "l"(p));
  return a;
}

__device__ __forceinline__ void cp16(uint32_t dst, const void* src) {
  asm volatile("cp.async.cg.shared.global [%0], [%1], 16;"
               :: "r"(dst), "l"(src) : "memory");
}

__device__ __forceinline__ void ldsm4(unsigned r[4], uint32_t addr) {
  asm volatile("ldmatrix.sync.aligned.m8n8.x4.shared.b16 {%0,%1,%2,%3}, [%4];"
               : "=r"(r[0]), "=r"(r[1]), "=r"(r[2]), "=r"(r[3]) : "r"(addr));
}

__device__ __forceinline__ void ldsm4t(unsigned r[4], uint32_t addr) {
  asm volatile("ldmatrix.sync.aligned.m8n8.x4.trans.shared.b16 {%0,%1,%2,%3}, [%4];"
               : "=r"(r[0]), "=r"(r[1]), "=r"(r[2]), "=r"(r[3]) : "r"(addr));
}

__device__ __forceinline__ void mma_f16(float d[4], const unsigned a[4],
                                        unsigned b0, unsigned b1) {
  asm volatile(
      "mma.sync.aligned.m16n8k16.row.col.f32.f16.f16.f32 "
      "{%0,%1,%2,%3}, {%4,%5,%6,%7}, {%8,%9}, {%0,%1,%2,%3};"
      : "+f"(d[0]), "+f"(d[1]), "+f"(d[2]), "+f"(d[3])
      : "r"(a[0]), "r"(a[1]), "r"(a[2]), "r"(a[3]), "r"(b0), "r"(b1));
}

__device__ __forceinline__ void split_store(__half* H, __half* L, size_t idx,
                                            float v) {
  __half h = __float2half_rn(v);
  H[idx] = h;
  L[idx] = __float2half_rn(v - __half2float(h));
}

// ---------------------------------------------------------------------------
// Prep kernels
// ---------------------------------------------------------------------------
// fp32 -> fp16, streaming (used for activations AND weights, layout-preserving)
__global__ void conv_h(const float4* __restrict__ X, uint2* __restrict__ Xh,
                       int n4) {
  int i = blockIdx.x * 256 + threadIdx.x;
  if (i >= n4) return;
  float4 v = X[i];
  __half2 h0 = __floats2half2_rn(v.x, v.y), h1 = __floats2half2_rn(v.z, v.w);
  uint2 ho;
  ho.x = *(unsigned*)&h0; ho.y = *(unsigned*)&h1;
  Xh[i] = ho;
}

// RoPE cos/sin table: g_rope[t*64 + d]
__global__ void rope_table_k(const int* __restrict__ positions) {
  int i = blockIdx.x * 256 + threadIdx.x;
  if (i >= T_SEQ * 64) return;
  int t = i >> 6, d = i & 63;
  float pos = (float)positions[t];
  float inv = expf(-((float)d * (1.0f / 64.0f)) * 13.815510557964274f);
  float fr = pos * inv;
  g_rope[i] = make_float2(cosf(fr), sinf(fr));
}

// Fused RoPE + fp16 conversion (table-driven; Q/K hi/lo, V hi only)
__global__ void rope_convert(const float* __restrict__ qkv) {
  const int t = blockIdx.x;
  const int tid = threadIdx.x;  // 256
  const float* row = qkv + (size_t)t * QKV_N;
  const float2* tab = g_rope + (size_t)t * 64;

  for (int i = tid; i < 2048; i += 256) {
    int head = i >> 6, d = i & 63;
    float2 cs = tab[d];
    float x1 = row[head * 128 + d], x2 = row[head * 128 + d + 64];
    size_t o = (size_t)t * 4096 + head * 128 + d;
    split_store(g_qh, g_ql, o,      (x1 * cs.x - x2 * cs.y) * ATTN_SCALE);
    split_store(g_qh, g_ql, o + 64, (x2 * cs.x + x1 * cs.y) * ATTN_SCALE);
  }
  for (int i = tid; i < 512; i += 256) {
    int head = i >> 6, d = i & 63;
    float2 cs = tab[d];
    float x1 = row[4096 + head * 128 + d], x2 = row[4096 + head * 128 + d + 64];
    size_t o = (size_t)t * 1024 + head * 128 + d;
    split_store(g_kh, g_kl, o,      x1 * cs.x - x2 * cs.y);
    split_store(g_kh, g_kl, o + 64, x2 * cs.x + x1 * cs.y);
  }
  for (int i = tid; i < 1024; i += 256)
    g_vh[(size_t)t * 1024 + i] = __float2half_rn(row[5120 + i]);
}

// ---------------------------------------------------------------------------
// 1-term fp16 GEMM, B in native [K,N] layout (trans-ldmatrix fragments).
// C[M,N] = fp16(A)[M,K] @ fp16(B)[K,N].
// BK=32, 4-stage cp.async (wait_group 2), 2 CTAs/SM, 8 warps (4Mx2N),
// warp tile 32x64, 16 distinct-acc MMAs per kst.
// A tile 128x64B swizzle seg^((row>>1)&3); B tile 32x256B swizzle seg^(row&7).
// ---------------------------------------------------------------------------
__global__ __launch_bounds__(256, 2) void gemm_h1t(
    const __half* __restrict__ pA, const __half* __restrict__ pB,
    float* __restrict__ C, int N, int K) {
  const uint32_t smb = smem_u32(dyn_smem);

  const int tid  = threadIdx.x;
  const int lane = tid & 31;
  const int warp = tid >> 5;
  const int wm = warp & 3;
  const int wn = warp >> 2;
  const int bm = blockIdx.y * 128;
  const int bn = blockIdx.x * 128;

  const __half* aP = pA + (size_t)bm * K;
  const __half* bP = pB + bn;

  // cp.async A: 2 threads/row, 2 segs each
  const int crow = tid >> 1;
  const int cs0  = (tid & 1) << 1;
  const int csw  = (crow >> 1) & 3;
  const uint32_t cd0 = (uint32_t)(crow * 64 + ((cs0 ^ csw) << 4));
  const uint32_t cd1 = (uint32_t)(crow * 64 + (((cs0 + 1) ^ csw) << 4));
  const int cse = cs0 << 3;

  // cp.async B: 8 threads/row (32 rows), 2 segs each of 16
  const int brow = tid >> 3;
  const int bs0  = (tid & 7) << 1;
  const int brx  = brow & 7;
  const uint32_t bd0 = (uint32_t)(brow * 256 + ((bs0 ^ brx) << 4));
  const uint32_t bd1 = (uint32_t)(brow * 256 + (((bs0 + 1) ^ brx) << 4));

  // A fragment geometry
  const int rowA = wm * 32 + (lane & 7) + ((lane >> 3) & 1) * 8;
  const int hcA  = (lane >> 4) & 1;
  const int swA  = (rowA >> 1) & 3;
  const uint32_t aofs = (uint32_t)(rowA * 64);
  const uint32_t xsa0 = (uint32_t)(((0 * 2 + hcA) ^ swA) << 4);
  const uint32_t xsa1 = (uint32_t)(((1 * 2 + hcA) ^ swA) << 4);

  // B fragment geometry (trans; same as attention V path)
  const int subm = lane >> 3;
  const int rVb  = (lane & 7) + ((subm & 1) << 3);  // 0..15
  const int hsB  = subm >> 1;                       // 0..1

  float acc[2][8][4];
#pragma unroll
  for (int i = 0; i < 2; i++)
#pragma unroll
    for (int j = 0; j < 8; j++)
#pragma unroll
      for (int r = 0; r < 4; r++) acc[i][j][r] = 0.f;

  const int NC = K >> 5;

#define ISSUE(c)                                                              \
  do {                                                                        \
    uint32_t sb = smb + (uint32_t)((c) & 3) * GSTG;                           \
    size_t ga = (size_t)crow * K + ((c) << 5) + cse;                          \
    cp16(sb + cd0, aP + ga); cp16(sb + cd1, aP + ga + 8);                     \
    size_t gb = (size_t)(((c) << 5) + brow) * N + bs0 * 8;                    \
    cp16(sb + GT + bd0, bP + gb); cp16(sb + GT + bd1, bP + gb + 8);           \
    asm volatile("cp.async.commit_group;" ::: "memory");                      \
  } while (0)

  ISSUE(0);
  ISSUE(1);
  ISSUE(2);

  for (int c = 0; c < NC; ++c) {
    asm volatile("cp.async.wait_group 2;" ::: "memory");
    __syncthreads();
    if (c + 3 < NC) ISSUE(c + 3);

    const uint32_t sb = smb + (uint32_t)(c & 3) * GSTG;
    const uint32_t ab = sb + aofs;
    const uint32_t bb = sb + GT;

#pragma unroll
    for (int kst = 0; kst < 2; ++kst) {
      const uint32_t xa = kst ? xsa1 : xsa0;
      const int rv = kst * 16 + rVb;
      const uint32_t bro = bb + (uint32_t)rv * 256;
      const int rxv = rv & 7;
      unsigned af[2][4], bf[4][4];
      ldsm4(af[0], ab + xa);
      ldsm4(af[1], ab + 1024 + xa);
#pragma unroll
      for (int p = 0; p < 4; ++p) {
        const int seg = wn * 8 + p * 2 + hsB;
        ldsm4t(bf[p], bro + (uint32_t)((seg ^ rxv) << 4));
      }
#pragma unroll
      for (int p = 0; p < 4; ++p)
#pragma unroll
        for (int mi = 0; mi < 2; ++mi)
#pragma unroll
          for (int sub = 0; sub < 2; ++sub)
            mma_f16(acc[mi][p * 2 + sub], af[mi], bf[p][sub * 2],
                    bf[p][sub * 2 + 1]);
    }
  }
#undef ISSUE

  const int g  = lane >> 2;
  const int tg = lane & 3;
#pragma unroll
  for (int mi = 0; mi < 2; mi++) {
    int r0 = bm + wm * 32 + mi * 16 + g;
#pragma unroll
    for (int ni = 0; ni < 8; ni++) {
      int c = bn + wn * 64 + ni * 8 + tg * 2;
      C[(size_t)r0 * N + c]           = acc[mi][ni][0];
      C[(size_t)r0 * N + c + 1]       = acc[mi][ni][1];
      C[(size_t)(r0 + 8) * N + c]     = acc[mi][ni][2];
      C[(size_t)(r0 + 8) * N + c + 1] = acc[mi][ni][3];
    }
  }
}

// ---------------------------------------------------------------------------
// Flash attention v3.1: 128-row Q tiles, 8 warps, double-buffered KV,
// 3-term S, 1-term PV (V fp16).  Epilogue fp16.
// ---------------------------------------------------------------------------
__global__ __launch_bounds__(256) void attn3(__half* __restrict__ oh) {
  char* smc = dyn_smem;
  const uint32_t smb = smem_u32(smc);

  const int h = blockIdx.x, qt = blockIdx.y;
  const int kvh = h >> 2;
  const int q0 = qt * 128;
  const int jmax = 2 * qt + 1;
  const int tid = threadIdx.x, lane = tid & 31, w = tid >> 5;
  const int g = lane >> 2, tg = lane & 3;

  // ---- Q tile load (once): 128 rows x 128 cols, hi+lo ----
  {
    const int row = tid >> 1, s0 = (tid & 1) * 8, rx = row & 7;
    const size_t gq = (size_t)(q0 + row) * 4096 + h * 128 + s0 * 8;
    const uint32_t dr = smb + row * 256;
#pragma unroll
    for (int s = 0; s < 8; ++s) {
      uint32_t d = dr + (((s0 + s) ^ rx) << 4);
      cp16(AQH + d, g_qh + gq + s * 8);
      cp16(AQL + d, g_ql + gq + s * 8);
    }
    asm volatile("cp.async.commit_group;" ::: "memory");
  }

  // KV: 64 rows, 3 tiles (Kh,Kl,Vh); thread -> row(tid>>2), 4 of 16 segs
  // but only 3 tiles now: use 4 threads/row, 4 segs, 3 arrays = 12 cp16... keep
  const int kvrow = tid >> 2, kvs0 = (tid & 3) * 4, kvrx = kvrow & 7;

#define KV_ISSUE(j, stg)                                                      \
  do {                                                                        \
    const uint32_t base = smb + AKV + (uint32_t)(stg) * AKVS;                 \
    const size_t gk = (size_t)((j) * 64 + kvrow) * 1024 + kvh * 128 + kvs0 * 8; \
    _Pragma("unroll")                                                         \
    for (int s = 0; s < 4; ++s) {                                             \
      uint32_t d = (uint32_t)(kvrow * 256 + (((kvs0 + s) ^ kvrx) << 4));      \
      cp16(base + d,         g_kh + gk + s * 8);                              \
      cp16(base + 16384 + d, g_kl + gk + s * 8);                              \
      cp16(base + 32768 + d, g_vh + gk + s * 8);                              \
    }                                                                         \
    asm volatile("cp.async.commit_group;" ::: "memory");                      \
  } while (0)

  KV_ISSUE(0, 0);

  const int rowA = w * 16 + (lane & 7) + ((lane >> 3) & 1) * 8;
  const int rxA = lane & 7;
  const int hcA = (lane >> 4) & 1;
  const uint32_t aQ = smb + (uint32_t)rowA * 256;
  const uint32_t aP = smb + APS + (uint32_t)rowA * 128;
  const int rBb = (lane & 7) + ((lane >> 4) & 1) * 8;
  const int hcB = (lane >> 3) & 1;
  const int subm = lane >> 3;
  const int rV = (lane & 7) + ((subm & 1) << 3);
  const int hsV = subm >> 1;

  float m0 = -1e30f, m1 = -1e30f, l0 = 0.f, l1 = 0.f;
  float O[16][4];
#pragma unroll
  for (int i = 0; i < 16; i++)
#pragma unroll
    for (int r = 0; r < 4; r++) O[i][r] = 0.f;

  for (int j = 0; j <= jmax; ++j) {
    __syncthreads();
    if (j < jmax) {
      KV_ISSUE(j + 1, (j + 1) & 1);
      asm volatile("cp.async.wait_group 1;" ::: "memory");
    } else {
      asm volatile("cp.async.wait_group 0;" ::: "memory");
    }
    __syncthreads();

    const uint32_t kvb = smb + AKV + (uint32_t)(j & 1) * AKVS;

    // ---- S = Qs K^T, 3-term fp16 ----
    float s[8][4];
#pragma unroll
    for (int ni = 0; ni < 8; ni++)
#pragma unroll
      for (int r = 0; r < 4; r++) s[ni][r] = 0.f;

#pragma unroll
    for (int kst = 0; kst < 8; ++kst) {
      unsigned qh[4], ql[4];
      const uint32_t xa = (uint32_t)(((kst * 2 + hcA) ^ rxA) << 4);
      ldsm4(qh, aQ + AQH + xa);
      ldsm4(ql, aQ + AQL + xa);
#pragma unroll
      for (int p = 0; p < 4; ++p) {
        const int rb = p * 16 + rBb;
        const uint32_t ab =
            kvb + (uint32_t)rb * 256 + (uint32_t)(((kst * 2 + hcB) ^ (rb & 7)) << 4);
        unsigned kh[4], kl[4];
        ldsm4(kh, ab);
        ldsm4(kl, ab + 16384);
        const int n0i = p * 2;
        mma_f16(s[n0i],     qh, kh[0], kh[1]);
        mma_f16(s[n0i + 1], qh, kh[2], kh[3]);
        mma_f16(s[n0i],     ql, kh[0], kh[1]);
        mma_f16(s[n0i + 1], ql, kh[2], kh[3]);
        mma_f16(s[n0i],     qh, kl[0], kl[1]);
        mma_f16(s[n0i + 1], qh, kl[2], kl[3]);
      }
    }

    // ---- online softmax ----
    const int gr0 = q0 + w * 16 + g;
    const int gr1 = gr0 + 8;
    float tm0 = -1e30f, tm1 = -1e30f;
#pragma unroll
    for (int ni = 0; ni < 8; ni++) {
#pragma unroll
      for (int cc = 0; cc < 2; cc++) {
        int gc = j * 64 + ni * 8 + tg * 2 + cc;
        float v0 = s[ni][cc];
        float v1 = s[ni][2 + cc];
        if (gc > gr0) v0 = -1e30f;
        if (gc > gr1) v1 = -1e30f;
        s[ni][cc] = v0;
        s[ni][2 + cc] = v1;
        tm0 = fmaxf(tm0, v0);
        tm1 = fmaxf(tm1, v1);
      }
    }
    tm0 = fmaxf(tm0, __shfl_xor_sync(0xffffffffu, tm0, 1));
    tm0 = fmaxf(tm0, __shfl_xor_sync(0xffffffffu, tm0, 2));
    tm1 = fmaxf(tm1, __shfl_xor_sync(0xffffffffu, tm1, 1));
    tm1 = fmaxf(tm1, __shfl_xor_sync(0xffffffffu, tm1, 2));

    float nm0 = fmaxf(m0, tm0), nm1 = fmaxf(m1, tm1);
    float a0 = __expf(m0 - nm0), a1 = __expf(m1 - nm1);

    const uint32_t pr0 = APS + (uint32_t)(w * 16 + g) * 128;
    const uint32_t pr1 = pr0 + 1024;
    float ps0 = 0.f, ps1 = 0.f;
#pragma unroll
    for (int ni = 0; ni < 8; ni++) {
      float p00 = __expf(s[ni][0] - nm0);
      float p01 = __expf(s[ni][1] - nm0);
      float p10 = __expf(s[ni][2] - nm1);
      float p11 = __expf(s[ni][3] - nm1);
      ps0 += p00 + p01;
      ps1 += p10 + p11;
      const uint32_t px = (uint32_t)(((ni ^ g) << 4) + tg * 4);
      *reinterpret_cast<__half2*>(smc + pr0 + px) = __floats2half2_rn(p00, p01);
      *reinterpret_cast<__half2*>(smc + pr1 + px) = __floats2half2_rn(p10, p11);
    }
    ps0 += __shfl_xor_sync(0xffffffffu, ps0, 1);
    ps0 += __shfl_xor_sync(0xffffffffu, ps0, 2);
    ps1 += __shfl_xor_sync(0xffffffffu, ps1, 1);
    ps1 += __shfl_xor_sync(0xffffffffu, ps1, 2);

    l0 = l0 * a0 + ps0;
    l1 = l1 * a1 + ps1;
    m0 = nm0;
    m1 = nm1;
#pragma unroll
    for (int ni = 0; ni < 16; ni++) {
      O[ni][0] *= a0; O[ni][1] *= a0;
      O[ni][2] *= a1; O[ni][3] *= a1;
    }
    __syncwarp();

    // ---- O += P V (single pass, V fp16) ----
#pragma unroll
    for (int k2 = 0; k2 < 4; ++k2) {
      unsigned pf[4];
      ldsm4(pf, aP + (uint32_t)(((k2 * 2 + hcA) ^ rxA) << 4));
      const int rv = k2 * 16 + rV;
      const uint32_t vb = kvb + 32768 + (uint32_t)rv * 256;
      const int rxv = rv & 7;
      unsigned vf[8][4];
#pragma unroll
      for (int dg = 0; dg < 8; ++dg)
        ldsm4t(vf[dg], vb + (uint32_t)(((dg * 2 + hsV) ^ rxv) << 4));
#pragma unroll
      for (int dg = 0; dg < 8; ++dg) {
        mma_f16(O[dg * 2],     pf, vf[dg][0], vf[dg][1]);
        mma_f16(O[dg * 2 + 1], pf, vf[dg][2], vf[dg][3]);
      }
    }
  }
#undef KV_ISSUE

  // epilogue -> fp16 (feeds 1-term Wo GEMM)
  const float inv0 = 1.f / l0;
  const float inv1 = 1.f / l1;
  const int r0 = q0 + w * 16 + g;
#pragma unroll
  for (int ni = 0; ni < 16; ni++) {
    const int c = h * HD + ni * 8 + tg * 2;
    const size_t i0 = (size_t)r0 * HID + c;
    const size_t i1 = (size_t)(r0 + 8) * HID + c;
    *reinterpret_cast<__half2*>(oh + i0) =
        __floats2half2_rn(O[ni][0] * inv0, O[ni][1] * inv0);
    *reinterpret_cast<__half2*>(oh + i1) =
        __floats2half2_rn(O[ni][2] * inv1, O[ni][3] * inv1);
  }
}

// ---------------------------------------------------------------------------
// launch
// ---------------------------------------------------------------------------
extern "C" void kernel_launch(void* const* d_in, const int* in_sizes, int n_in,
                              void* d_out, int out_size) {
  (void)in_sizes; (void)n_in; (void)out_size;
  const int*   positions = (const int*)d_in[0];
  const float* hidden    = (const float*)d_in[1];
  const float* Wqkv      = (const float*)d_in[2];
  const float* Wo        = (const float*)d_in[3];
  float* out = (float*)d_out;

  float* qkv_p;
  __half *ah, *wq16, *wo16;
  cudaGetSymbolAddress((void**)&qkv_p, g_qkv);
  cudaGetSymbolAddress((void**)&ah, g_ah);
  cudaGetSymbolAddress((void**)&wq16, g_wq16);
  cudaGetSymbolAddress((void**)&wo16, g_wo16);

  cudaFuncSetAttribute(gemm_h1t, cudaFuncAttributeMaxDynamicSharedMemorySize,
                       GEMM_SMEM);
  cudaFuncSetAttribute(attn3, cudaFuncAttributeMaxDynamicSharedMemorySize,
                       ATTN_SMEM);

  // Prep: pure streaming converts (no transpose), RoPE table
  conv_h<<<(HID * QKV_N / 4 + 255) / 256, 256>>>(
      (const float4*)Wqkv, (uint2*)wq16, HID * QKV_N / 4);
  conv_h<<<(HID * HID / 4 + 255) / 256, 256>>>(
      (const float4*)Wo, (uint2*)wo16, HID * HID / 4);
  conv_h<<<(T_SEQ * HID / 4 + 255) / 256, 256>>>(
      (const float4*)hidden, (uint2*)ah, T_SEQ * HID / 4);
  rope_table_k<<<(T_SEQ * 64 + 255) / 256, 256>>>(positions);

  // 1) QKV projection (1-term fp16, B native [K,N])
  gemm_h1t<<<dim3(QKV_N / 128, T_SEQ / 128), 256, GEMM_SMEM>>>(
      ah, wq16, qkv_p, QKV_N, HID);
  // 2) RoPE + fp16 conversion (table-driven)
  rope_convert<<<T_SEQ, 256>>>(qkv_p);
  // 3) Flash attention (writes fp16 into g_ah)
  attn3<<<dim3(NHEADS, T_SEQ / 128), 256, ATTN_SMEM>>>(ah);
  // 4) Output projection
  gemm_h1t<<<dim3(HID / 128, T_SEQ / 128), 256, GEMM_SMEM>>>(
      ah, wo16, out, HID, HID);
}

// round 14
// speedup vs baseline: 1.7951x; 1.0915x over previous
#include <cuda_runtime.h>
#include <cuda_fp16.h>
#include <cstdint>

#define T_SEQ 2048
#define HID   4096
#define QKV_N 6144
#define HD    128
#define NHEADS 32
#define ATTN_SCALE 0.08838834764831845f   // 128^-0.5

// GEMM: BM=BN=128, BK=32 (fp16). A tile 128x64B (8KB), B tile 32x256B (8KB,
// [K,N] layout, trans-ldmatrix). 4 stages, 2 CTAs/SM.
#define GT 8192
#define GSTG 16384
#define GEMM_SMEM (4 * GSTG)   // 64KB

// Attention: Q 128x128 fp16 (32KB) + 2-stage KV (Kh,Kl,Vh 48KB each) + P 16KB
#define AQH 0
#define AKV 32768
#define AKVS 49152
#define APS (AKV + 2 * AKVS)      // 131072
#define ATTN_SMEM (APS + 16384)   // 147456

extern __shared__ char dyn_smem[];

// ---------------------------------------------------------------------------
// Scratch (allocation-free rule: __device__ globals)
// ---------------------------------------------------------------------------
__device__ float g_qkv[(size_t)T_SEQ * QKV_N];
__device__ __align__(16) __half g_ah[(size_t)T_SEQ * HID];    // GEMM A (fp16)
__device__ __align__(16) __half g_wq16[(size_t)HID * QKV_N];  // Wqkv fp16 [K,N]
__device__ __align__(16) __half g_wo16[(size_t)HID * HID];    // Wo fp16 [K,N]
__device__ __align__(16) __half g_qh[(size_t)T_SEQ * HID];    // roped+scaled Q fp16
__device__ __align__(16) __half g_kh[(size_t)T_SEQ * 1024];   // roped K hi
__device__ __align__(16) __half g_kl[(size_t)T_SEQ * 1024];   // roped K lo
__device__ __align__(16) __half g_vh[(size_t)T_SEQ * 1024];   // V (fp16)
__device__ __align__(8) float2 g_rope[(size_t)T_SEQ * 64];    // cos/sin table

// ---------------------------------------------------------------------------
// helpers
// ---------------------------------------------------------------------------
__device__ __forceinline__ uint32_t smem_u32(const void* p) {
  uint32_t a;
  asm("{ .reg .u64 t; cvta.to.shared.u64 t, %1; cvt.u32.u64 %0, t; }"
      : "=r"(a) : "l"(p));
  return a;
}

__device__ __forceinline__ void cp16(uint32_t dst, const void* src) {
  asm volatile("cp.async.cg.shared.global [%0], [%1], 16;"
               :: "r"(dst), "l"(src) : "memory");
}

__device__ __forceinline__ void ldsm4(unsigned r[4], uint32_t addr) {
  asm volatile("ldmatrix.sync.aligned.m8n8.x4.shared.b16 {%0,%1,%2,%3}, [%4];"
               : "=r"(r[0]), "=r"(r[1]), "=r"(r[2]), "=r"(r[3]) : "r"(addr));
}

__device__ __forceinline__ void ldsm4t(unsigned r[4], uint32_t addr) {
  asm volatile("ldmatrix.sync.aligned.m8n8.x4.trans.shared.b16 {%0,%1,%2,%3}, [%4];"
               : "=r"(r[0]), "=r"(r[1]), "=r"(r[2]), "=r"(r[3]) : "r"(addr));
}

__device__ __forceinline__ void mma_f16(float d[4], const unsigned a[4],
                                        unsigned b0, unsigned b1) {
  asm volatile(
      "mma.sync.aligned.m16n8k16.row.col.f32.f16.f16.f32 "
      "{%0,%1,%2,%3}, {%4,%5,%6,%7}, {%8,%9}, {%0,%1,%2,%3};"
      : "+f"(d[0]), "+f"(d[1]), "+f"(d[2]), "+f"(d[3])
      : "r"(a[0]), "r"(a[1]), "r"(a[2]), "r"(a[3]), "r"(b0), "r"(b1));
}

__device__ __forceinline__ void split_store(__half* H, __half* L, size_t idx,
                                            float v) {
  __half h = __float2half_rn(v);
  H[idx] = h;
  L[idx] = __float2half_rn(v - __half2float(h));
}

// ---------------------------------------------------------------------------
// Prep kernels
// ---------------------------------------------------------------------------
// fp32 -> fp16, streaming (activations AND weights, layout-preserving)
__global__ void conv_h(const float4* __restrict__ X, uint2* __restrict__ Xh,
                       int n4) {
  int i = blockIdx.x * 256 + threadIdx.x;
  if (i >= n4) return;
  float4 v = X[i];
  __half2 h0 = __floats2half2_rn(v.x, v.y), h1 = __floats2half2_rn(v.z, v.w);
  uint2 ho;
  ho.x = *(unsigned*)&h0; ho.y = *(unsigned*)&h1;
  Xh[i] = ho;
}

// RoPE cos/sin table: g_rope[t*64 + d]
__global__ void rope_table_k(const int* __restrict__ positions) {
  int i = blockIdx.x * 256 + threadIdx.x;
  if (i >= T_SEQ * 64) return;
  int t = i >> 6, d = i & 63;
  float pos = (float)positions[t];
  float inv = expf(-((float)d * (1.0f / 64.0f)) * 13.815510557964274f);
  float fr = pos * inv;
  g_rope[i] = make_float2(cosf(fr), sinf(fr));
}

// Fused RoPE + fp16 conversion (table-driven; Q fp16, K hi/lo, V fp16)
__global__ void rope_convert(const float* __restrict__ qkv) {
  const int t = blockIdx.x;
  const int tid = threadIdx.x;  // 256
  const float* row = qkv + (size_t)t * QKV_N;
  const float2* tab = g_rope + (size_t)t * 64;

  for (int i = tid; i < 2048; i += 256) {
    int head = i >> 6, d = i & 63;
    float2 cs = tab[d];
    float x1 = row[head * 128 + d], x2 = row[head * 128 + d + 64];
    size_t o = (size_t)t * 4096 + head * 128 + d;
    g_qh[o]      = __float2half_rn((x1 * cs.x - x2 * cs.y) * ATTN_SCALE);
    g_qh[o + 64] = __float2half_rn((x2 * cs.x + x1 * cs.y) * ATTN_SCALE);
  }
  for (int i = tid; i < 512; i += 256) {
    int head = i >> 6, d = i & 63;
    float2 cs = tab[d];
    float x1 = row[4096 + head * 128 + d], x2 = row[4096 + head * 128 + d + 64];
    size_t o = (size_t)t * 1024 + head * 128 + d;
    split_store(g_kh, g_kl, o,      x1 * cs.x - x2 * cs.y);
    split_store(g_kh, g_kl, o + 64, x2 * cs.x + x1 * cs.y);
  }
  for (int i = tid; i < 1024; i += 256)
    g_vh[(size_t)t * 1024 + i] = __float2half_rn(row[5120 + i]);
}

// ---------------------------------------------------------------------------
// 1-term fp16 GEMM, B in native [K,N] layout (trans-ldmatrix fragments).
// (proven round-13 config)
// ---------------------------------------------------------------------------
__global__ __launch_bounds__(256, 2) void gemm_h1t(
    const __half* __restrict__ pA, const __half* __restrict__ pB,
    float* __restrict__ C, int N, int K) {
  const uint32_t smb = smem_u32(dyn_smem);

  const int tid  = threadIdx.x;
  const int lane = tid & 31;
  const int warp = tid >> 5;
  const int wm = warp & 3;
  const int wn = warp >> 2;
  const int bm = blockIdx.y * 128;
  const int bn = blockIdx.x * 128;

  const __half* aP = pA + (size_t)bm * K;
  const __half* bP = pB + bn;

  const int crow = tid >> 1;
  const int cs0  = (tid & 1) << 1;
  const int csw  = (crow >> 1) & 3;
  const uint32_t cd0 = (uint32_t)(crow * 64 + ((cs0 ^ csw) << 4));
  const uint32_t cd1 = (uint32_t)(crow * 64 + (((cs0 + 1) ^ csw) << 4));
  const int cse = cs0 << 3;

  const int brow = tid >> 3;
  const int bs0  = (tid & 7) << 1;
  const int brx  = brow & 7;
  const uint32_t bd0 = (uint32_t)(brow * 256 + ((bs0 ^ brx) << 4));
  const uint32_t bd1 = (uint32_t)(brow * 256 + (((bs0 + 1) ^ brx) << 4));

  const int rowA = wm * 32 + (lane & 7) + ((lane >> 3) & 1) * 8;
  const int hcA  = (lane >> 4) & 1;
  const int swA  = (rowA >> 1) & 3;
  const uint32_t aofs = (uint32_t)(rowA * 64);
  const uint32_t xsa0 = (uint32_t)(((0 * 2 + hcA) ^ swA) << 4);
  const uint32_t xsa1 = (uint32_t)(((1 * 2 + hcA) ^ swA) << 4);

  const int subm = lane >> 3;
  const int rVb  = (lane & 7) + ((subm & 1) << 3);
  const int hsB  = subm >> 1;

  float acc[2][8][4];
#pragma unroll
  for (int i = 0; i < 2; i++)
#pragma unroll
    for (int j = 0; j < 8; j++)
#pragma unroll
      for (int r = 0; r < 4; r++) acc[i][j][r] = 0.f;

  const int NC = K >> 5;

#define ISSUE(c)                                                              \
  do {                                                                        \
    uint32_t sb = smb + (uint32_t)((c) & 3) * GSTG;                           \
    size_t ga = (size_t)crow * K + ((c) << 5) + cse;                          \
    cp16(sb + cd0, aP + ga); cp16(sb + cd1, aP + ga + 8);                     \
    size_t gb = (size_t)(((c) << 5) + brow) * N + bs0 * 8;                    \
    cp16(sb + GT + bd0, bP + gb); cp16(sb + GT + bd1, bP + gb + 8);           \
    asm volatile("cp.async.commit_group;" ::: "memory");                      \
  } while (0)

  ISSUE(0);
  ISSUE(1);
  ISSUE(2);

  for (int c = 0; c < NC; ++c) {
    asm volatile("cp.async.wait_group 2;" ::: "memory");
    __syncthreads();
    if (c + 3 < NC) ISSUE(c + 3);

    const uint32_t sb = smb + (uint32_t)(c & 3) * GSTG;
    const uint32_t ab = sb + aofs;
    const uint32_t bb = sb + GT;

#pragma unroll
    for (int kst = 0; kst < 2; ++kst) {
      const uint32_t xa = kst ? xsa1 : xsa0;
      const int rv = kst * 16 + rVb;
      const uint32_t bro = bb + (uint32_t)rv * 256;
      const int rxv = rv & 7;
      unsigned af[2][4], bf[4][4];
      ldsm4(af[0], ab + xa);
      ldsm4(af[1], ab + 1024 + xa);
#pragma unroll
      for (int p = 0; p < 4; ++p) {
        const int seg = wn * 8 + p * 2 + hsB;
        ldsm4t(bf[p], bro + (uint32_t)((seg ^ rxv) << 4));
      }
#pragma unroll
      for (int p = 0; p < 4; ++p)
#pragma unroll
        for (int mi = 0; mi < 2; ++mi)
#pragma unroll
          for (int sub = 0; sub < 2; ++sub)
            mma_f16(acc[mi][p * 2 + sub], af[mi], bf[p][sub * 2],
                    bf[p][sub * 2 + 1]);
    }
  }
#undef ISSUE

  const int g  = lane >> 2;
  const int tg = lane & 3;
#pragma unroll
  for (int mi = 0; mi < 2; mi++) {
    int r0 = bm + wm * 32 + mi * 16 + g;
#pragma unroll
    for (int ni = 0; ni < 8; ni++) {
      int c = bn + wn * 64 + ni * 8 + tg * 2;
      C[(size_t)r0 * N + c]           = acc[mi][ni][0];
      C[(size_t)r0 * N + c + 1]       = acc[mi][ni][1];
      C[(size_t)(r0 + 8) * N + c]     = acc[mi][ni][2];
      C[(size_t)(r0 + 8) * N + c + 1] = acc[mi][ni][3];
    }
  }
}

// ---------------------------------------------------------------------------
// Flash attention v3.2: 128-row Q tiles, 8 warps, double-buffered KV,
// 2-term S (Q fp16 x K hi/lo), 1-term PV (V fp16). Heavy tiles launch first.
// ---------------------------------------------------------------------------
__global__ __launch_bounds__(256) void attn3(__half* __restrict__ oh) {
  char* smc = dyn_smem;
  const uint32_t smb = smem_u32(smc);

  const int h = blockIdx.x;
  const int qt = (gridDim.y - 1) - blockIdx.y;   // heavy (large-qt) tiles first
  const int kvh = h >> 2;
  const int q0 = qt * 128;
  const int jmax = 2 * qt + 1;
  const int tid = threadIdx.x, lane = tid & 31, w = tid >> 5;
  const int g = lane >> 2, tg = lane & 3;

  // ---- Q tile load (once): 128 rows x 128 cols fp16 ----
  {
    const int row = tid >> 1, s0 = (tid & 1) * 8, rx = row & 7;
    const size_t gq = (size_t)(q0 + row) * 4096 + h * 128 + s0 * 8;
    const uint32_t dr = smb + row * 256;
#pragma unroll
    for (int s = 0; s < 8; ++s) {
      uint32_t d = dr + (((s0 + s) ^ rx) << 4);
      cp16(AQH + d, g_qh + gq + s * 8);
    }
    asm volatile("cp.async.commit_group;" ::: "memory");
  }

  const int kvrow = tid >> 2, kvs0 = (tid & 3) * 4, kvrx = kvrow & 7;

#define KV_ISSUE(j, stg)                                                      \
  do {                                                                        \
    const uint32_t base = smb + AKV + (uint32_t)(stg) * AKVS;                 \
    const size_t gk = (size_t)((j) * 64 + kvrow) * 1024 + kvh * 128 + kvs0 * 8; \
    _Pragma("unroll")                                                         \
    for (int s = 0; s < 4; ++s) {                                             \
      uint32_t d = (uint32_t)(kvrow * 256 + (((kvs0 + s) ^ kvrx) << 4));      \
      cp16(base + d,         g_kh + gk + s * 8);                              \
      cp16(base + 16384 + d, g_kl + gk + s * 8);                              \
      cp16(base + 32768 + d, g_vh + gk + s * 8);                              \
    }                                                                         \
    asm volatile("cp.async.commit_group;" ::: "memory");                      \
  } while (0)

  KV_ISSUE(0, 0);

  const int rowA = w * 16 + (lane & 7) + ((lane >> 3) & 1) * 8;
  const int rxA = lane & 7;
  const int hcA = (lane >> 4) & 1;
  const uint32_t aQ = smb + (uint32_t)rowA * 256;
  const uint32_t aP = smb + APS + (uint32_t)rowA * 128;
  const int rBb = (lane & 7) + ((lane >> 4) & 1) * 8;
  const int hcB = (lane >> 3) & 1;
  const int subm = lane >> 3;
  const int rV = (lane & 7) + ((subm & 1) << 3);
  const int hsV = subm >> 1;

  float m0 = -1e30f, m1 = -1e30f, l0 = 0.f, l1 = 0.f;
  float O[16][4];
#pragma unroll
  for (int i = 0; i < 16; i++)
#pragma unroll
    for (int r = 0; r < 4; r++) O[i][r] = 0.f;

  for (int j = 0; j <= jmax; ++j) {
    __syncthreads();
    if (j < jmax) {
      KV_ISSUE(j + 1, (j + 1) & 1);
      asm volatile("cp.async.wait_group 1;" ::: "memory");
    } else {
      asm volatile("cp.async.wait_group 0;" ::: "memory");
    }
    __syncthreads();

    const uint32_t kvb = smb + AKV + (uint32_t)(j & 1) * AKVS;

    // ---- S = Qs K^T, 2-term (Q fp16 x (Kh + Kl)) ----
    float s[8][4];
#pragma unroll
    for (int ni = 0; ni < 8; ni++)
#pragma unroll
      for (int r = 0; r < 4; r++) s[ni][r] = 0.f;

#pragma unroll
    for (int kst = 0; kst < 8; ++kst) {
      unsigned qh[4];
      const uint32_t xa = (uint32_t)(((kst * 2 + hcA) ^ rxA) << 4);
      ldsm4(qh, aQ + xa);
#pragma unroll
      for (int p = 0; p < 4; ++p) {
        const int rb = p * 16 + rBb;
        const uint32_t ab =
            kvb + (uint32_t)rb * 256 + (uint32_t)(((kst * 2 + hcB) ^ (rb & 7)) << 4);
        unsigned kh[4], kl[4];
        ldsm4(kh, ab);
        ldsm4(kl, ab + 16384);
        const int n0i = p * 2;
        mma_f16(s[n0i],     qh, kh[0], kh[1]);
        mma_f16(s[n0i + 1], qh, kh[2], kh[3]);
        mma_f16(s[n0i],     qh, kl[0], kl[1]);
        mma_f16(s[n0i + 1], qh, kl[2], kl[3]);
      }
    }

    // ---- online softmax ----
    const int gr0 = q0 + w * 16 + g;
    const int gr1 = gr0 + 8;
    float tm0 = -1e30f, tm1 = -1e30f;
#pragma unroll
    for (int ni = 0; ni < 8; ni++) {
#pragma unroll
      for (int cc = 0; cc < 2; cc++) {
        int gc = j * 64 + ni * 8 + tg * 2 + cc;
        float v0 = s[ni][cc];
        float v1 = s[ni][2 + cc];
        if (gc > gr0) v0 = -1e30f;
        if (gc > gr1) v1 = -1e30f;
        s[ni][cc] = v0;
        s[ni][2 + cc] = v1;
        tm0 = fmaxf(tm0, v0);
        tm1 = fmaxf(tm1, v1);
      }
    }
    tm0 = fmaxf(tm0, __shfl_xor_sync(0xffffffffu, tm0, 1));
    tm0 = fmaxf(tm0, __shfl_xor_sync(0xffffffffu, tm0, 2));
    tm1 = fmaxf(tm1, __shfl_xor_sync(0xffffffffu, tm1, 1));
    tm1 = fmaxf(tm1, __shfl_xor_sync(0xffffffffu, tm1, 2));

    float nm0 = fmaxf(m0, tm0), nm1 = fmaxf(m1, tm1);
    float a0 = __expf(m0 - nm0), a1 = __expf(m1 - nm1);

    const uint32_t pr0 = APS + (uint32_t)(w * 16 + g) * 128;
    const uint32_t pr1 = pr0 + 1024;
    float ps0 = 0.f, ps1 = 0.f;
#pragma unroll
    for (int ni = 0; ni < 8; ni++) {
      float p00 = __expf(s[ni][0] - nm0);
      float p01 = __expf(s[ni][1] - nm0);
      float p10 = __expf(s[ni][2] - nm1);
      float p11 = __expf(s[ni][3] - nm1);
      ps0 += p00 + p01;
      ps1 += p10 + p11;
      const uint32_t px = (uint32_t)(((ni ^ g) << 4) + tg * 4);
      *reinterpret_cast<__half2*>(smc + pr0 + px) = __floats2half2_rn(p00, p01);
      *reinterpret_cast<__half2*>(smc + pr1 + px) = __floats2half2_rn(p10, p11);
    }
    ps0 += __shfl_xor_sync(0xffffffffu, ps0, 1);
    ps0 += __shfl_xor_sync(0xffffffffu, ps0, 2);
    ps1 += __shfl_xor_sync(0xffffffffu, ps1, 1);
    ps1 += __shfl_xor_sync(0xffffffffu, ps1, 2);

    l0 = l0 * a0 + ps0;
    l1 = l1 * a1 + ps1;
    m0 = nm0;
    m1 = nm1;
#pragma unroll
    for (int ni = 0; ni < 16; ni++) {
      O[ni][0] *= a0; O[ni][1] *= a0;
      O[ni][2] *= a1; O[ni][3] *= a1;
    }
    __syncwarp();

    // ---- O += P V (single pass, V fp16) ----
#pragma unroll
    for (int k2 = 0; k2 < 4; ++k2) {
      unsigned pf[4];
      ldsm4(pf, aP + (uint32_t)(((k2 * 2 + hcA) ^ rxA) << 4));
      const int rv = k2 * 16 + rV;
      const uint32_t vb = kvb + 32768 + (uint32_t)rv * 256;
      const int rxv = rv & 7;
      unsigned vf[8][4];
#pragma unroll
      for (int dg = 0; dg < 8; ++dg)
        ldsm4t(vf[dg], vb + (uint32_t)(((dg * 2 + hsV) ^ rxv) << 4));
#pragma unroll
      for (int dg = 0; dg < 8; ++dg) {
        mma_f16(O[dg * 2],     pf, vf[dg][0], vf[dg][1]);
        mma_f16(O[dg * 2 + 1], pf, vf[dg][2], vf[dg][3]);
      }
    }
  }
#undef KV_ISSUE

  // epilogue -> fp16 (feeds 1-term Wo GEMM)
  const float inv0 = 1.f / l0;
  const float inv1 = 1.f / l1;
  const int r0 = q0 + w * 16 + g;
#pragma unroll
  for (int ni = 0; ni < 16; ni++) {
    const int c = h * HD + ni * 8 + tg * 2;
    const size_t i0 = (size_t)r0 * HID + c;
    const size_t i1 = (size_t)(r0 + 8) * HID + c;
    *reinterpret_cast<__half2*>(oh + i0) =
        __floats2half2_rn(O[ni][0] * inv0, O[ni][1] * inv0);
    *reinterpret_cast<__half2*>(oh + i1) =
        __floats2half2_rn(O[ni][2] * inv1, O[ni][3] * inv1);
  }
}

// ---------------------------------------------------------------------------
// launch
// ---------------------------------------------------------------------------
extern "C" void kernel_launch(void* const* d_in, const int* in_sizes, int n_in,
                              void* d_out, int out_size) {
  (void)in_sizes; (void)n_in; (void)out_size;
  const int*   positions = (const int*)d_in[0];
  const float* hidden    = (const float*)d_in[1];
  const float* Wqkv      = (const float*)d_in[2];
  const float* Wo        = (const float*)d_in[3];
  float* out = (float*)d_out;

  float* qkv_p;
  __half *ah, *wq16, *wo16;
  cudaGetSymbolAddress((void**)&qkv_p, g_qkv);
  cudaGetSymbolAddress((void**)&ah, g_ah);
  cudaGetSymbolAddress((void**)&wq16, g_wq16);
  cudaGetSymbolAddress((void**)&wo16, g_wo16);

  cudaFuncSetAttribute(gemm_h1t, cudaFuncAttributeMaxDynamicSharedMemorySize,
                       GEMM_SMEM);
  cudaFuncSetAttribute(attn3, cudaFuncAttributeMaxDynamicSharedMemorySize,
                       ATTN_SMEM);

  // Prep: streaming converts, RoPE table
  conv_h<<<(HID * QKV_N / 4 + 255) / 256, 256>>>(
      (const float4*)Wqkv, (uint2*)wq16, HID * QKV_N / 4);
  conv_h<<<(HID * HID / 4 + 255) / 256, 256>>>(
      (const float4*)Wo, (uint2*)wo16, HID * HID / 4);
  conv_h<<<(T_SEQ * HID / 4 + 255) / 256, 256>>>(
      (const float4*)hidden, (uint2*)ah, T_SEQ * HID / 4);
  rope_table_k<<<(T_SEQ * 64 + 255) / 256, 256>>>(positions);

  // 1) QKV projection (1-term fp16, B native [K,N])
  gemm_h1t<<<dim3(QKV_N / 128, T_SEQ / 128), 256, GEMM_SMEM>>>(
      ah, wq16, qkv_p, QKV_N, HID);
  // 2) RoPE + fp16 conversion (table-driven)
  rope_convert<<<T_SEQ, 256>>>(qkv_p);
  // 3) Flash attention (writes fp16 into g_ah)
  attn3<<<dim3(NHEADS, T_SEQ / 128), 256, ATTN_SMEM>>>(ah);
  // 4) Output projection
  gemm_h1t<<<dim3(HID / 128, T_SEQ / 128), 256, GEMM_SMEM>>>(
      ah, wo16, out, HID, HID);
}

// round 15
// speedup vs baseline: 1.8594x; 1.0358x over previous
#include <cuda_runtime.h>
#include <cuda_fp16.h>
#include <cstdint>

#define T_SEQ 2048
#define HID   4096
#define QKV_N 6144
#define HD    128
#define NHEADS 32
#define ATTN_SCALE 0.08838834764831845f   // 128^-0.5

// GEMM: BM=BN=128, BK=32 (fp16). A tile 128x64B (8KB), B tile 32x256B (8KB,
// [K,N] layout, trans-ldmatrix). 4 stages, 2 CTAs/SM.
// Epilogue (fused-rope mode) stages the fp32 C tile: 128 x 132 floats.
#define GT 8192
#define GSTG 16384
#define GEMM_SMEM (128 * 132 * 4)   // 67584 >= 4*GSTG

// Attention: Q 128x128 fp16 (32KB) + 2-stage KV (Kh,Kl,Vh 48KB each) + P 16KB
#define AQH 0
#define AKV 32768
#define AKVS 49152
#define APS (AKV + 2 * AKVS)      // 131072
#define ATTN_SMEM (APS + 16384)   // 147456

extern __shared__ char dyn_smem[];

// ---------------------------------------------------------------------------
// Scratch (allocation-free rule: __device__ globals)
// ---------------------------------------------------------------------------
__device__ __align__(16) __half g_ah[(size_t)T_SEQ * HID];    // GEMM A (fp16)
__device__ __align__(16) __half g_wq16[(size_t)HID * QKV_N];  // Wqkv fp16 [K,N]
__device__ __align__(16) __half g_wo16[(size_t)HID * HID];    // Wo fp16 [K,N]
__device__ __align__(16) __half g_qh[(size_t)T_SEQ * HID];    // roped+scaled Q fp16
__device__ __align__(16) __half g_kh[(size_t)T_SEQ * 1024];   // roped K hi
__device__ __align__(16) __half g_kl[(size_t)T_SEQ * 1024];   // roped K lo
__device__ __align__(16) __half g_vh[(size_t)T_SEQ * 1024];   // V (fp16)
__device__ __align__(8) float2 g_rope[(size_t)T_SEQ * 64];    // cos/sin table

// ---------------------------------------------------------------------------
// helpers
// ---------------------------------------------------------------------------
__device__ __forceinline__ uint32_t smem_u32(const void* p) {
  uint32_t a;
  asm("{ .reg .u64 t; cvta.to.shared.u64 t, %1; cvt.u32.u64 %0, t; }"
      : "=r"(a) : "l"(p));
  return a;
}

__device__ __forceinline__ void cp16(uint32_t dst, const void* src) {
  asm volatile("cp.async.cg.shared.global [%0], [%1], 16;"
               :: "r"(dst), "l"(src) : "memory");
}

__device__ __forceinline__ void ldsm4(unsigned r[4], uint32_t addr) {
  asm volatile("ldmatrix.sync.aligned.m8n8.x4.shared.b16 {%0,%1,%2,%3}, [%4];"
               : "=r"(r[0]), "=r"(r[1]), "=r"(r[2]), "=r"(r[3]) : "r"(addr));
}

__device__ __forceinline__ void ldsm4t(unsigned r[4], uint32_t addr) {
  asm volatile("ldmatrix.sync.aligned.m8n8.x4.trans.shared.b16 {%0,%1,%2,%3}, [%4];"
               : "=r"(r[0]), "=r"(r[1]), "=r"(r[2]), "=r"(r[3]) : "r"(addr));
}

__device__ __forceinline__ void mma_f16(float d[4], const unsigned a[4],
                                        unsigned b0, unsigned b1) {
  asm volatile(
      "mma.sync.aligned.m16n8k16.row.col.f32.f16.f16.f32 "
      "{%0,%1,%2,%3}, {%4,%5,%6,%7}, {%8,%9}, {%0,%1,%2,%3};"
      : "+f"(d[0]), "+f"(d[1]), "+f"(d[2]), "+f"(d[3])
      : "r"(a[0]), "r"(a[1]), "r"(a[2]), "r"(a[3]), "r"(b0), "r"(b1));
}

__device__ __forceinline__ void split_store(__half* H, __half* L, size_t idx,
                                            float v) {
  __half h = __float2half_rn(v);
  H[idx] = h;
  L[idx] = __float2half_rn(v - __half2float(h));
}

// ---------------------------------------------------------------------------
// Prep kernels
// ---------------------------------------------------------------------------
// fp32 -> fp16, streaming (activations AND weights, layout-preserving)
__global__ void conv_h(const float4* __restrict__ X, uint2* __restrict__ Xh,
                       int n4) {
  int i = blockIdx.x * 256 + threadIdx.x;
  if (i >= n4) return;
  float4 v = X[i];
  __half2 h0 = __floats2half2_rn(v.x, v.y), h1 = __floats2half2_rn(v.z, v.w);
  uint2 ho;
  ho.x = *(unsigned*)&h0; ho.y = *(unsigned*)&h1;
  Xh[i] = ho;
}

// RoPE cos/sin table: g_rope[t*64 + d]
__global__ void rope_table_k(const int* __restrict__ positions) {
  int i = blockIdx.x * 256 + threadIdx.x;
  if (i >= T_SEQ * 64) return;
  int t = i >> 6, d = i & 63;
  float pos = (float)positions[t];
  float inv = expf(-((float)d * (1.0f / 64.0f)) * 13.815510557964274f);
  float fr = pos * inv;
  g_rope[i] = make_float2(cosf(fr), sinf(fr));
}

// ---------------------------------------------------------------------------
// 1-term fp16 GEMM, B in native [K,N] layout (trans-ldmatrix fragments).
// MODE 0: plain fp32 C store (Wo projection).
// MODE 1: fused RoPE epilogue (QKV projection): stages C tile in smem, then
//   head<32  -> rope+scale -> g_qh   (fp16)
//   head<40  -> rope       -> g_kh/g_kl (hi/lo)
//   else     -> convert    -> g_vh   (fp16)
// ---------------------------------------------------------------------------
template <int MODE>
__global__ __launch_bounds__(256, 2) void gemm_h1t(
    const __half* __restrict__ pA, const __half* __restrict__ pB,
    float* __restrict__ C, int N, int K) {
  const uint32_t smb = smem_u32(dyn_smem);

  const int tid  = threadIdx.x;
  const int lane = tid & 31;
  const int warp = tid >> 5;
  const int wm = warp & 3;
  const int wn = warp >> 2;
  const int bm = blockIdx.y * 128;
  const int bn = blockIdx.x * 128;

  const __half* aP = pA + (size_t)bm * K;
  const __half* bP = pB + bn;

  const int crow = tid >> 1;
  const int cs0  = (tid & 1) << 1;
  const int csw  = (crow >> 1) & 3;
  const uint32_t cd0 = (uint32_t)(crow * 64 + ((cs0 ^ csw) << 4));
  const uint32_t cd1 = (uint32_t)(crow * 64 + (((cs0 + 1) ^ csw) << 4));
  const int cse = cs0 << 3;

  const int brow = tid >> 3;
  const int bs0  = (tid & 7) << 1;
  const int brx  = brow & 7;
  const uint32_t bd0 = (uint32_t)(brow * 256 + ((bs0 ^ brx) << 4));
  const uint32_t bd1 = (uint32_t)(brow * 256 + (((bs0 + 1) ^ brx) << 4));

  const int rowA = wm * 32 + (lane & 7) + ((lane >> 3) & 1) * 8;
  const int hcA  = (lane >> 4) & 1;
  const int swA  = (rowA >> 1) & 3;
  const uint32_t aofs = (uint32_t)(rowA * 64);
  const uint32_t xsa0 = (uint32_t)(((0 * 2 + hcA) ^ swA) << 4);
  const uint32_t xsa1 = (uint32_t)(((1 * 2 + hcA) ^ swA) << 4);

  const int subm = lane >> 3;
  const int rVb  = (lane & 7) + ((subm & 1) << 3);
  const int hsB  = subm >> 1;

  float acc[2][8][4];
#pragma unroll
  for (int i = 0; i < 2; i++)
#pragma unroll
    for (int j = 0; j < 8; j++)
#pragma unroll
      for (int r = 0; r < 4; r++) acc[i][j][r] = 0.f;

  const int NC = K >> 5;

#define ISSUE(c)                                                              \
  do {                                                                        \
    uint32_t sb = smb + (uint32_t)((c) & 3) * GSTG;                           \
    size_t ga = (size_t)crow * K + ((c) << 5) + cse;                          \
    cp16(sb + cd0, aP + ga); cp16(sb + cd1, aP + ga + 8);                     \
    size_t gb = (size_t)(((c) << 5) + brow) * N + bs0 * 8;                    \
    cp16(sb + GT + bd0, bP + gb); cp16(sb + GT + bd1, bP + gb + 8);           \
    asm volatile("cp.async.commit_group;" ::: "memory");                      \
  } while (0)

  ISSUE(0);
  ISSUE(1);
  ISSUE(2);

  for (int c = 0; c < NC; ++c) {
    asm volatile("cp.async.wait_group 2;" ::: "memory");
    __syncthreads();
    if (c + 3 < NC) ISSUE(c + 3);
    else asm volatile("cp.async.commit_group;" ::: "memory");  // keep group math exact

    const uint32_t sb = smb + (uint32_t)(c & 3) * GSTG;
    const uint32_t ab = sb + aofs;
    const uint32_t bb = sb + GT;

#pragma unroll
    for (int kst = 0; kst < 2; ++kst) {
      const uint32_t xa = kst ? xsa1 : xsa0;
      const int rv = kst * 16 + rVb;
      const uint32_t bro = bb + (uint32_t)rv * 256;
      const int rxv = rv & 7;
      unsigned af[2][4], bf[4][4];
      ldsm4(af[0], ab + xa);
      ldsm4(af[1], ab + 1024 + xa);
#pragma unroll
      for (int p = 0; p < 4; ++p) {
        const int seg = wn * 8 + p * 2 + hsB;
        ldsm4t(bf[p], bro + (uint32_t)((seg ^ rxv) << 4));
      }
#pragma unroll
      for (int p = 0; p < 4; ++p)
#pragma unroll
        for (int mi = 0; mi < 2; ++mi)
#pragma unroll
          for (int sub = 0; sub < 2; ++sub)
            mma_f16(acc[mi][p * 2 + sub], af[mi], bf[p][sub * 2],
                    bf[p][sub * 2 + 1]);
    }
  }
#undef ISSUE

  const int g  = lane >> 2;
  const int tg = lane & 3;

  if (MODE == 0) {
#pragma unroll
    for (int mi = 0; mi < 2; mi++) {
      int r0 = bm + wm * 32 + mi * 16 + g;
#pragma unroll
      for (int ni = 0; ni < 8; ni++) {
        int c = bn + wn * 64 + ni * 8 + tg * 2;
        C[(size_t)r0 * N + c]           = acc[mi][ni][0];
        C[(size_t)r0 * N + c + 1]       = acc[mi][ni][1];
        C[(size_t)(r0 + 8) * N + c]     = acc[mi][ni][2];
        C[(size_t)(r0 + 8) * N + c + 1] = acc[mi][ni][3];
      }
    }
    return;
  }

  // ---- MODE 1: fused RoPE epilogue ----
  asm volatile("cp.async.wait_group 0;" ::: "memory");
  __syncthreads();  // all mainloop smem reads done; safe to reuse stages
  float* csm = reinterpret_cast<float*>(dyn_smem);  // pitch 132 floats
#pragma unroll
  for (int mi = 0; mi < 2; mi++) {
    int r0 = wm * 32 + mi * 16 + g;
#pragma unroll
    for (int ni = 0; ni < 8; ni++) {
      int cc = wn * 64 + ni * 8 + tg * 2;
      csm[r0 * 132 + cc]           = acc[mi][ni][0];
      csm[r0 * 132 + cc + 1]       = acc[mi][ni][1];
      csm[(r0 + 8) * 132 + cc]     = acc[mi][ni][2];
      csm[(r0 + 8) * 132 + cc + 1] = acc[mi][ni][3];
    }
  }
  __syncthreads();

  const int head = bn >> 7;  // 0..47 (one head per N-tile)
  if (head < 32) {
    // Q: rope + scale
    for (int i = tid; i < 128 * 64; i += 256) {
      int r = i >> 6, d = i & 63;
      int t = bm + r;
      float2 rc = g_rope[(size_t)t * 64 + d];
      float x1 = csm[r * 132 + d], x2 = csm[r * 132 + d + 64];
      size_t o = (size_t)t * 4096 + head * 128 + d;
      g_qh[o]      = __float2half_rn((x1 * rc.x - x2 * rc.y) * ATTN_SCALE);
      g_qh[o + 64] = __float2half_rn((x2 * rc.x + x1 * rc.y) * ATTN_SCALE);
    }
  } else if (head < 40) {
    // K: rope, hi/lo split
    const int kh = head - 32;
    for (int i = tid; i < 128 * 64; i += 256) {
      int r = i >> 6, d = i & 63;
      int t = bm + r;
      float2 rc = g_rope[(size_t)t * 64 + d];
      float x1 = csm[r * 132 + d], x2 = csm[r * 132 + d + 64];
      size_t o = (size_t)t * 1024 + kh * 128 + d;
      split_store(g_kh, g_kl, o,      x1 * rc.x - x2 * rc.y);
      split_store(g_kh, g_kl, o + 64, x2 * rc.x + x1 * rc.y);
    }
  } else {
    // V: straight fp16
    const int vh = head - 40;
    for (int i = tid; i < 128 * 128; i += 256) {
      int r = i >> 7, d = i & 127;
      g_vh[(size_t)(bm + r) * 1024 + vh * 128 + d] =
          __float2half_rn(csm[r * 132 + d]);
    }
  }
}

// ---------------------------------------------------------------------------
// Flash attention v3.2 (proven round-14): 128-row Q tiles, 8 warps,
// double-buffered KV, 2-term S, 1-term PV, heavy tiles first.
// ---------------------------------------------------------------------------
__global__ __launch_bounds__(256) void attn3(__half* __restrict__ oh) {
  char* smc = dyn_smem;
  const uint32_t smb = smem_u32(smc);

  const int h = blockIdx.x;
  const int qt = (gridDim.y - 1) - blockIdx.y;
  const int kvh = h >> 2;
  const int q0 = qt * 128;
  const int jmax = 2 * qt + 1;
  const int tid = threadIdx.x, lane = tid & 31, w = tid >> 5;
  const int g = lane >> 2, tg = lane & 3;

  {
    const int row = tid >> 1, s0 = (tid & 1) * 8, rx = row & 7;
    const size_t gq = (size_t)(q0 + row) * 4096 + h * 128 + s0 * 8;
    const uint32_t dr = smb + row * 256;
#pragma unroll
    for (int s = 0; s < 8; ++s) {
      uint32_t d = dr + (((s0 + s) ^ rx) << 4);
      cp16(AQH + d, g_qh + gq + s * 8);
    }
    asm volatile("cp.async.commit_group;" ::: "memory");
  }

  const int kvrow = tid >> 2, kvs0 = (tid & 3) * 4, kvrx = kvrow & 7;

#define KV_ISSUE(j, stg)                                                      \
  do {                                                                        \
    const uint32_t base = smb + AKV + (uint32_t)(stg) * AKVS;                 \
    const size_t gk = (size_t)((j) * 64 + kvrow) * 1024 + kvh * 128 + kvs0 * 8; \
    _Pragma("unroll")                                                         \
    for (int s = 0; s < 4; ++s) {                                             \
      uint32_t d = (uint32_t)(kvrow * 256 + (((kvs0 + s) ^ kvrx) << 4));      \
      cp16(base + d,         g_kh + gk + s * 8);                              \
      cp16(base + 16384 + d, g_kl + gk + s * 8);                              \
      cp16(base + 32768 + d, g_vh + gk + s * 8);                              \
    }                                                                         \
    asm volatile("cp.async.commit_group;" ::: "memory");                      \
  } while (0)

  KV_ISSUE(0, 0);

  const int rowA = w * 16 + (lane & 7) + ((lane >> 3) & 1) * 8;
  const int rxA = lane & 7;
  const int hcA = (lane >> 4) & 1;
  const uint32_t aQ = smb + (uint32_t)rowA * 256;
  const uint32_t aP = smb + APS + (uint32_t)rowA * 128;
  const int rBb = (lane & 7) + ((lane >> 4) & 1) * 8;
  const int hcB = (lane >> 3) & 1;
  const int subm = lane >> 3;
  const int rV = (lane & 7) + ((subm & 1) << 3);
  const int hsV = subm >> 1;

  float m0 = -1e30f, m1 = -1e30f, l0 = 0.f, l1 = 0.f;
  float O[16][4];
#pragma unroll
  for (int i = 0; i < 16; i++)
#pragma unroll
    for (int r = 0; r < 4; r++) O[i][r] = 0.f;

  for (int j = 0; j <= jmax; ++j) {
    __syncthreads();
    if (j < jmax) {
      KV_ISSUE(j + 1, (j + 1) & 1);
      asm volatile("cp.async.wait_group 1;" ::: "memory");
    } else {
      asm volatile("cp.async.wait_group 0;" ::: "memory");
    }
    __syncthreads();

    const uint32_t kvb = smb + AKV + (uint32_t)(j & 1) * AKVS;

    // ---- S = Qs K^T, 2-term (Q fp16 x (Kh + Kl)) ----
    float s[8][4];
#pragma unroll
    for (int ni = 0; ni < 8; ni++)
#pragma unroll
      for (int r = 0; r < 4; r++) s[ni][r] = 0.f;

#pragma unroll
    for (int kst = 0; kst < 8; ++kst) {
      unsigned qh[4];
      const uint32_t xa = (uint32_t)(((kst * 2 + hcA) ^ rxA) << 4);
      ldsm4(qh, aQ + xa);
#pragma unroll
      for (int p = 0; p < 4; ++p) {
        const int rb = p * 16 + rBb;
        const uint32_t ab =
            kvb + (uint32_t)rb * 256 + (uint32_t)(((kst * 2 + hcB) ^ (rb & 7)) << 4);
        unsigned kh[4], kl[4];
        ldsm4(kh, ab);
        ldsm4(kl, ab + 16384);
        const int n0i = p * 2;
        mma_f16(s[n0i],     qh, kh[0], kh[1]);
        mma_f16(s[n0i + 1], qh, kh[2], kh[3]);
        mma_f16(s[n0i],     qh, kl[0], kl[1]);
        mma_f16(s[n0i + 1], qh, kl[2], kl[3]);
      }
    }

    // ---- online softmax ----
    const int gr0 = q0 + w * 16 + g;
    const int gr1 = gr0 + 8;
    float tm0 = -1e30f, tm1 = -1e30f;
#pragma unroll
    for (int ni = 0; ni < 8; ni++) {
#pragma unroll
      for (int cc = 0; cc < 2; cc++) {
        int gc = j * 64 + ni * 8 + tg * 2 + cc;
        float v0 = s[ni][cc];
        float v1 = s[ni][2 + cc];
        if (gc > gr0) v0 = -1e30f;
        if (gc > gr1) v1 = -1e30f;
        s[ni][cc] = v0;
        s[ni][2 + cc] = v1;
        tm0 = fmaxf(tm0, v0);
        tm1 = fmaxf(tm1, v1);
      }
    }
    tm0 = fmaxf(tm0, __shfl_xor_sync(0xffffffffu, tm0, 1));
    tm0 = fmaxf(tm0, __shfl_xor_sync(0xffffffffu, tm0, 2));
    tm1 = fmaxf(tm1, __shfl_xor_sync(0xffffffffu, tm1, 1));
    tm1 = fmaxf(tm1, __shfl_xor_sync(0xffffffffu, tm1, 2));

    float nm0 = fmaxf(m0, tm0), nm1 = fmaxf(m1, tm1);
    float a0 = __expf(m0 - nm0), a1 = __expf(m1 - nm1);

    const uint32_t pr0 = APS + (uint32_t)(w * 16 + g) * 128;
    const uint32_t pr1 = pr0 + 1024;
    float ps0 = 0.f, ps1 = 0.f;
#pragma unroll
    for (int ni = 0; ni < 8; ni++) {
      float p00 = __expf(s[ni][0] - nm0);
      float p01 = __expf(s[ni][1] - nm0);
      float p10 = __expf(s[ni][2] - nm1);
      float p11 = __expf(s[ni][3] - nm1);
      ps0 += p00 + p01;
      ps1 += p10 + p11;
      const uint32_t px = (uint32_t)(((ni ^ g) << 4) + tg * 4);
      *reinterpret_cast<__half2*>(smc + pr0 + px) = __floats2half2_rn(p00, p01);
      *reinterpret_cast<__half2*>(smc + pr1 + px) = __floats2half2_rn(p10, p11);
    }
    ps0 += __shfl_xor_sync(0xffffffffu, ps0, 1);
    ps0 += __shfl_xor_sync(0xffffffffu, ps0, 2);
    ps1 += __shfl_xor_sync(0xffffffffu, ps1, 1);
    ps1 += __shfl_xor_sync(0xffffffffu, ps1, 2);

    l0 = l0 * a0 + ps0;
    l1 = l1 * a1 + ps1;
    m0 = nm0;
    m1 = nm1;
#pragma unroll
    for (int ni = 0; ni < 16; ni++) {
      O[ni][0] *= a0; O[ni][1] *= a0;
      O[ni][2] *= a1; O[ni][3] *= a1;
    }
    __syncwarp();

    // ---- O += P V (single pass, V fp16) ----
#pragma unroll
    for (int k2 = 0; k2 < 4; ++k2) {
      unsigned pf[4];
      ldsm4(pf, aP + (uint32_t)(((k2 * 2 + hcA) ^ rxA) << 4));
      const int rv = k2 * 16 + rV;
      const uint32_t vb = kvb + 32768 + (uint32_t)rv * 256;
      const int rxv = rv & 7;
      unsigned vf[8][4];
#pragma unroll
      for (int dg = 0; dg < 8; ++dg)
        ldsm4t(vf[dg], vb + (uint32_t)(((dg * 2 + hsV) ^ rxv) << 4));
#pragma unroll
      for (int dg = 0; dg < 8; ++dg) {
        mma_f16(O[dg * 2],     pf, vf[dg][0], vf[dg][1]);
        mma_f16(O[dg * 2 + 1], pf, vf[dg][2], vf[dg][3]);
      }
    }
  }
#undef KV_ISSUE

  // epilogue -> fp16 (feeds 1-term Wo GEMM)
  const float inv0 = 1.f / l0;
  const float inv1 = 1.f / l1;
  const int r0 = q0 + w * 16 + g;
#pragma unroll
  for (int ni = 0; ni < 16; ni++) {
    const int c = h * HD + ni * 8 + tg * 2;
    const size_t i0 = (size_t)r0 * HID + c;
    const size_t i1 = (size_t)(r0 + 8) * HID + c;
    *reinterpret_cast<__half2*>(oh + i0) =
        __floats2half2_rn(O[ni][0] * inv0, O[ni][1] * inv0);
    *reinterpret_cast<__half2*>(oh + i1) =
        __floats2half2_rn(O[ni][2] * inv1, O[ni][3] * inv1);
  }
}

// ---------------------------------------------------------------------------
// launch
// ---------------------------------------------------------------------------
extern "C" void kernel_launch(void* const* d_in, const int* in_sizes, int n_in,
                              void* d_out, int out_size) {
  (void)in_sizes; (void)n_in; (void)out_size;
  const int*   positions = (const int*)d_in[0];
  const float* hidden    = (const float*)d_in[1];
  const float* Wqkv      = (const float*)d_in[2];
  const float* Wo        = (const float*)d_in[3];
  float* out = (float*)d_out;

  __half *ah, *wq16, *wo16;
  cudaGetSymbolAddress((void**)&ah, g_ah);
  cudaGetSymbolAddress((void**)&wq16, g_wq16);
  cudaGetSymbolAddress((void**)&wo16, g_wo16);

  cudaFuncSetAttribute(gemm_h1t<0>, cudaFuncAttributeMaxDynamicSharedMemorySize,
                       GEMM_SMEM);
  cudaFuncSetAttribute(gemm_h1t<1>, cudaFuncAttributeMaxDynamicSharedMemorySize,
                       GEMM_SMEM);
  cudaFuncSetAttribute(attn3, cudaFuncAttributeMaxDynamicSharedMemorySize,
                       ATTN_SMEM);

  // Prep: streaming converts + RoPE table (table feeds the fused GEMM epilogue)
  conv_h<<<(HID * QKV_N / 4 + 255) / 256, 256>>>(
      (const float4*)Wqkv, (uint2*)wq16, HID * QKV_N / 4);
  conv_h<<<(HID * HID / 4 + 255) / 256, 256>>>(
      (const float4*)Wo, (uint2*)wo16, HID * HID / 4);
  conv_h<<<(T_SEQ * HID / 4 + 255) / 256, 256>>>(
      (const float4*)hidden, (uint2*)ah, T_SEQ * HID / 4);
  rope_table_k<<<(T_SEQ * 64 + 255) / 256, 256>>>(positions);

  // 1) QKV projection with fused RoPE epilogue (writes g_qh/g_kh/g_kl/g_vh)
  gemm_h1t<1><<<dim3(QKV_N / 128, T_SEQ / 128), 256, GEMM_SMEM>>>(
      ah, wq16, nullptr, QKV_N, HID);
  // 2) Flash attention (writes fp16 into g_ah)
  attn3<<<dim3(NHEADS, T_SEQ / 128), 256, ATTN_SMEM>>>(ah);
  // 3) Output projection
  gemm_h1t<0><<<dim3(HID / 128, T_SEQ / 128), 256, GEMM_SMEM>>>(
      ah, wo16, out, HID, HID);
}

// round 16
// speedup vs baseline: 1.9133x; 1.0290x over previous
#include <cuda_runtime.h>
#include <cuda_fp16.h>
#include <cstdint>

#define T_SEQ 2048
#define HID   4096
#define QKV_N 6144
#define HD    128
#define NHEADS 32
#define ATTN_SCALE 0.08838834764831845f   // 128^-0.5

// GEMM: BM=BN=128, BK=32 (fp16). A tile 128x64B (8KB), B tile 32x256B (8KB,
// [K,N] layout, trans-ldmatrix). 4 stages, 2 CTAs/SM.
// Epilogue (fused-rope mode) stages the fp32 C tile: 128 x 132 floats.
#define GT 8192
#define GSTG 16384
#define GEMM_SMEM (128 * 132 * 4)   // 67584 >= 4*GSTG

// Attention v4: Q 256x128 fp16 (64KB) + 2-stage KV (Kh,Kl,Vh 48KB each)
// + P 256x64 fp16 (32KB)
#define AQH 0
#define AKV 65536
#define AKVS 49152
#define APS (AKV + 2 * AKVS)      // 163840
#define ATTN_SMEM (APS + 32768)   // 196608

extern __shared__ char dyn_smem[];

// ---------------------------------------------------------------------------
// Scratch (allocation-free rule: __device__ globals)
// ---------------------------------------------------------------------------
__device__ __align__(16) __half g_ah[(size_t)T_SEQ * HID];    // GEMM A (fp16)
__device__ __align__(16) __half g_wq16[(size_t)HID * QKV_N];  // Wqkv fp16 [K,N]
__device__ __align__(16) __half g_wo16[(size_t)HID * HID];    // Wo fp16 [K,N]
__device__ __align__(16) __half g_qh[(size_t)T_SEQ * HID];    // roped+scaled Q fp16
__device__ __align__(16) __half g_kh[(size_t)T_SEQ * 1024];   // roped K hi
__device__ __align__(16) __half g_kl[(size_t)T_SEQ * 1024];   // roped K lo
__device__ __align__(16) __half g_vh[(size_t)T_SEQ * 1024];   // V (fp16)
__device__ __align__(8) float2 g_rope[(size_t)T_SEQ * 64];    // cos/sin table

// ---------------------------------------------------------------------------
// helpers
// ---------------------------------------------------------------------------
__device__ __forceinline__ uint32_t smem_u32(const void* p) {
  uint32_t a;
  asm("{ .reg .u64 t; cvta.to.shared.u64 t, %1; cvt.u32.u64 %0, t; }"
      : "=r"(a) : "l"(p));
  return a;
}

__device__ __forceinline__ void cp16(uint32_t dst, const void* src) {
  asm volatile("cp.async.cg.shared.global [%0], [%1], 16;"
               :: "r"(dst), "l"(src) : "memory");
}

__device__ __forceinline__ void ldsm4(unsigned r[4], uint32_t addr) {
  asm volatile("ldmatrix.sync.aligned.m8n8.x4.shared.b16 {%0,%1,%2,%3}, [%4];"
               : "=r"(r[0]), "=r"(r[1]), "=r"(r[2]), "=r"(r[3]) : "r"(addr));
}

__device__ __forceinline__ void ldsm4t(unsigned r[4], uint32_t addr) {
  asm volatile("ldmatrix.sync.aligned.m8n8.x4.trans.shared.b16 {%0,%1,%2,%3}, [%4];"
               : "=r"(r[0]), "=r"(r[1]), "=r"(r[2]), "=r"(r[3]) : "r"(addr));
}

__device__ __forceinline__ void mma_f16(float d[4], const unsigned a[4],
                                        unsigned b0, unsigned b1) {
  asm volatile(
      "mma.sync.aligned.m16n8k16.row.col.f32.f16.f16.f32 "
      "{%0,%1,%2,%3}, {%4,%5,%6,%7}, {%8,%9}, {%0,%1,%2,%3};"
      : "+f"(d[0]), "+f"(d[1]), "+f"(d[2]), "+f"(d[3])
      : "r"(a[0]), "r"(a[1]), "r"(a[2]), "r"(a[3]), "r"(b0), "r"(b1));
}

__device__ __forceinline__ void split_store(__half* H, __half* L, size_t idx,
                                            float v) {
  __half h = __float2half_rn(v);
  H[idx] = h;
  L[idx] = __float2half_rn(v - __half2float(h));
}

// ---------------------------------------------------------------------------
// Single merged prep kernel: Wqkv conv | Wo conv | hidden conv | rope table
// ---------------------------------------------------------------------------
__global__ void prep_all(const float4* __restrict__ Wq, const float4* __restrict__ Wo,
                         const float4* __restrict__ H, const int* __restrict__ pos) {
  const size_t nq = (size_t)HID * QKV_N / 4;
  const size_t no = (size_t)HID * HID / 4;
  const size_t nh = (size_t)T_SEQ * HID / 4;
  size_t i = (size_t)blockIdx.x * 256 + threadIdx.x;

  if (i < nq) {
    float4 v = Wq[i];
    __half2 h0 = __floats2half2_rn(v.x, v.y), h1 = __floats2half2_rn(v.z, v.w);
    uint2 ho; ho.x = *(unsigned*)&h0; ho.y = *(unsigned*)&h1;
    reinterpret_cast<uint2*>(g_wq16)[i] = ho;
    return;
  }
  i -= nq;
  if (i < no) {
    float4 v = Wo[i];
    __half2 h0 = __floats2half2_rn(v.x, v.y), h1 = __floats2half2_rn(v.z, v.w);
    uint2 ho; ho.x = *(unsigned*)&h0; ho.y = *(unsigned*)&h1;
    reinterpret_cast<uint2*>(g_wo16)[i] = ho;
    return;
  }
  i -= no;
  if (i < nh) {
    float4 v = H[i];
    __half2 h0 = __floats2half2_rn(v.x, v.y), h1 = __floats2half2_rn(v.z, v.w);
    uint2 ho; ho.x = *(unsigned*)&h0; ho.y = *(unsigned*)&h1;
    reinterpret_cast<uint2*>(g_ah)[i] = ho;
    return;
  }
  i -= nh;
  if (i < (size_t)T_SEQ * 64) {
    int t = (int)(i >> 6), d = (int)(i & 63);
    float p = (float)pos[t];
    float inv = expf(-((float)d * (1.0f / 64.0f)) * 13.815510557964274f);
    float fr = p * inv;
    g_rope[i] = make_float2(cosf(fr), sinf(fr));
  }
}

// ---------------------------------------------------------------------------
// 1-term fp16 GEMM, B in native [K,N] layout (trans-ldmatrix fragments).
// MODE 0: plain fp32 C store (Wo). MODE 1: fused RoPE epilogue (QKV).
// (proven round-15 config)
// ---------------------------------------------------------------------------
template <int MODE>
__global__ __launch_bounds__(256, 2) void gemm_h1t(
    const __half* __restrict__ pA, const __half* __restrict__ pB,
    float* __restrict__ C, int N, int K) {
  const uint32_t smb = smem_u32(dyn_smem);

  const int tid  = threadIdx.x;
  const int lane = tid & 31;
  const int warp = tid >> 5;
  const int wm = warp & 3;
  const int wn = warp >> 2;
  const int bm = blockIdx.y * 128;
  const int bn = blockIdx.x * 128;

  const __half* aP = pA + (size_t)bm * K;
  const __half* bP = pB + bn;

  const int crow = tid >> 1;
  const int cs0  = (tid & 1) << 1;
  const int csw  = (crow >> 1) & 3;
  const uint32_t cd0 = (uint32_t)(crow * 64 + ((cs0 ^ csw) << 4));
  const uint32_t cd1 = (uint32_t)(crow * 64 + (((cs0 + 1) ^ csw) << 4));
  const int cse = cs0 << 3;

  const int brow = tid >> 3;
  const int bs0  = (tid & 7) << 1;
  const int brx  = brow & 7;
  const uint32_t bd0 = (uint32_t)(brow * 256 + ((bs0 ^ brx) << 4));
  const uint32_t bd1 = (uint32_t)(brow * 256 + (((bs0 + 1) ^ brx) << 4));

  const int rowA = wm * 32 + (lane & 7) + ((lane >> 3) & 1) * 8;
  const int hcA  = (lane >> 4) & 1;
  const int swA  = (rowA >> 1) & 3;
  const uint32_t aofs = (uint32_t)(rowA * 64);
  const uint32_t xsa0 = (uint32_t)(((0 * 2 + hcA) ^ swA) << 4);
  const uint32_t xsa1 = (uint32_t)(((1 * 2 + hcA) ^ swA) << 4);

  const int subm = lane >> 3;
  const int rVb  = (lane & 7) + ((subm & 1) << 3);
  const int hsB  = subm >> 1;

  float acc[2][8][4];
#pragma unroll
  for (int i = 0; i < 2; i++)
#pragma unroll
    for (int j = 0; j < 8; j++)
#pragma unroll
      for (int r = 0; r < 4; r++) acc[i][j][r] = 0.f;

  const int NC = K >> 5;

#define ISSUE(c)                                                              \
  do {                                                                        \
    uint32_t sb = smb + (uint32_t)((c) & 3) * GSTG;                           \
    size_t ga = (size_t)crow * K + ((c) << 5) + cse;                          \
    cp16(sb + cd0, aP + ga); cp16(sb + cd1, aP + ga + 8);                     \
    size_t gb = (size_t)(((c) << 5) + brow) * N + bs0 * 8;                    \
    cp16(sb + GT + bd0, bP + gb); cp16(sb + GT + bd1, bP + gb + 8);           \
    asm volatile("cp.async.commit_group;" ::: "memory");                      \
  } while (0)

  ISSUE(0);
  ISSUE(1);
  ISSUE(2);

  for (int c = 0; c < NC; ++c) {
    asm volatile("cp.async.wait_group 2;" ::: "memory");
    __syncthreads();
    if (c + 3 < NC) ISSUE(c + 3);
    else asm volatile("cp.async.commit_group;" ::: "memory");

    const uint32_t sb = smb + (uint32_t)(c & 3) * GSTG;
    const uint32_t ab = sb + aofs;
    const uint32_t bb = sb + GT;

#pragma unroll
    for (int kst = 0; kst < 2; ++kst) {
      const uint32_t xa = kst ? xsa1 : xsa0;
      const int rv = kst * 16 + rVb;
      const uint32_t bro = bb + (uint32_t)rv * 256;
      const int rxv = rv & 7;
      unsigned af[2][4], bf[4][4];
      ldsm4(af[0], ab + xa);
      ldsm4(af[1], ab + 1024 + xa);
#pragma unroll
      for (int p = 0; p < 4; ++p) {
        const int seg = wn * 8 + p * 2 + hsB;
        ldsm4t(bf[p], bro + (uint32_t)((seg ^ rxv) << 4));
      }
#pragma unroll
      for (int p = 0; p < 4; ++p)
#pragma unroll
        for (int mi = 0; mi < 2; ++mi)
#pragma unroll
          for (int sub = 0; sub < 2; ++sub)
            mma_f16(acc[mi][p * 2 + sub], af[mi], bf[p][sub * 2],
                    bf[p][sub * 2 + 1]);
    }
  }
#undef ISSUE

  const int g  = lane >> 2;
  const int tg = lane & 3;

  if (MODE == 0) {
#pragma unroll
    for (int mi = 0; mi < 2; mi++) {
      int r0 = bm + wm * 32 + mi * 16 + g;
#pragma unroll
      for (int ni = 0; ni < 8; ni++) {
        int c = bn + wn * 64 + ni * 8 + tg * 2;
        C[(size_t)r0 * N + c]           = acc[mi][ni][0];
        C[(size_t)r0 * N + c + 1]       = acc[mi][ni][1];
        C[(size_t)(r0 + 8) * N + c]     = acc[mi][ni][2];
        C[(size_t)(r0 + 8) * N + c + 1] = acc[mi][ni][3];
      }
    }
    return;
  }

  // ---- MODE 1: fused RoPE epilogue ----
  asm volatile("cp.async.wait_group 0;" ::: "memory");
  __syncthreads();
  float* csm = reinterpret_cast<float*>(dyn_smem);  // pitch 132 floats
#pragma unroll
  for (int mi = 0; mi < 2; mi++) {
    int r0 = wm * 32 + mi * 16 + g;
#pragma unroll
    for (int ni = 0; ni < 8; ni++) {
      int cc = wn * 64 + ni * 8 + tg * 2;
      csm[r0 * 132 + cc]           = acc[mi][ni][0];
      csm[r0 * 132 + cc + 1]       = acc[mi][ni][1];
      csm[(r0 + 8) * 132 + cc]     = acc[mi][ni][2];
      csm[(r0 + 8) * 132 + cc + 1] = acc[mi][ni][3];
    }
  }
  __syncthreads();

  const int head = bn >> 7;
  if (head < 32) {
    for (int i = tid; i < 128 * 64; i += 256) {
      int r = i >> 6, d = i & 63;
      int t = bm + r;
      float2 rc = g_rope[(size_t)t * 64 + d];
      float x1 = csm[r * 132 + d], x2 = csm[r * 132 + d + 64];
      size_t o = (size_t)t * 4096 + head * 128 + d;
      g_qh[o]      = __float2half_rn((x1 * rc.x - x2 * rc.y) * ATTN_SCALE);
      g_qh[o + 64] = __float2half_rn((x2 * rc.x + x1 * rc.y) * ATTN_SCALE);
    }
  } else if (head < 40) {
    const int kh = head - 32;
    for (int i = tid; i < 128 * 64; i += 256) {
      int r = i >> 6, d = i & 63;
      int t = bm + r;
      float2 rc = g_rope[(size_t)t * 64 + d];
      float x1 = csm[r * 132 + d], x2 = csm[r * 132 + d + 64];
      size_t o = (size_t)t * 1024 + kh * 128 + d;
      split_store(g_kh, g_kl, o,      x1 * rc.x - x2 * rc.y);
      split_store(g_kh, g_kl, o + 64, x2 * rc.x + x1 * rc.y);
    }
  } else {
    const int vh = head - 40;
    for (int i = tid; i < 128 * 128; i += 256) {
      int r = i >> 7, d = i & 127;
      g_vh[(size_t)(bm + r) * 1024 + vh * 128 + d] =
          __float2half_rn(csm[r * 132 + d]);
    }
  }
}

// ---------------------------------------------------------------------------
// Flash attention v4: 256-row Q tiles, 512 threads / 16 warps (16 rows each),
// double-buffered KV, 2-term S, 1-term PV, heavy tiles first.
// Per-warp arithmetic identical to proven round-14 kernel.
// ---------------------------------------------------------------------------
__global__ __launch_bounds__(512) void attn4(__half* __restrict__ oh) {
  char* smc = dyn_smem;
  const uint32_t smb = smem_u32(smc);

  const int h = blockIdx.x;
  const int qt = (gridDim.y - 1) - blockIdx.y;   // heavy tiles first
  const int kvh = h >> 2;
  const int q0 = qt * 256;
  const int jmax = 4 * qt + 3;
  const int tid = threadIdx.x, lane = tid & 31, w = tid >> 5;
  const int g = lane >> 2, tg = lane & 3;

  // ---- Q tile load (once): 256 rows x 128 cols fp16 ----
  {
    const int row = tid >> 1, s0 = (tid & 1) * 8, rx = row & 7;
    const size_t gq = (size_t)(q0 + row) * 4096 + h * 128 + s0 * 8;
    const uint32_t dr = smb + row * 256;
#pragma unroll
    for (int s = 0; s < 8; ++s) {
      uint32_t d = dr + (((s0 + s) ^ rx) << 4);
      cp16(AQH + d, g_qh + gq + s * 8);
    }
    asm volatile("cp.async.commit_group;" ::: "memory");
  }

  // KV: 64 rows x 16 segs x 3 arrays; 512 threads -> 8/row, 2 segs each
  const int kvrow = tid >> 3, kvs0 = (tid & 7) * 2, kvrx = kvrow & 7;

#define KV_ISSUE(j, stg)                                                      \
  do {                                                                        \
    const uint32_t base = smb + AKV + (uint32_t)(stg) * AKVS;                 \
    const size_t gk = (size_t)((j) * 64 + kvrow) * 1024 + kvh * 128 + kvs0 * 8; \
    _Pragma("unroll")                                                         \
    for (int s = 0; s < 2; ++s) {                                             \
      uint32_t d = (uint32_t)(kvrow * 256 + (((kvs0 + s) ^ kvrx) << 4));      \
      cp16(base + d,         g_kh + gk + s * 8);                              \
      cp16(base + 16384 + d, g_kl + gk + s * 8);                              \
      cp16(base + 32768 + d, g_vh + gk + s * 8);                              \
    }                                                                         \
    asm volatile("cp.async.commit_group;" ::: "memory");                      \
  } while (0)

  KV_ISSUE(0, 0);

  const int rowA = w * 16 + (lane & 7) + ((lane >> 3) & 1) * 8;
  const int rxA = lane & 7;
  const int hcA = (lane >> 4) & 1;
  const uint32_t aQ = smb + (uint32_t)rowA * 256;
  const uint32_t aP = smb + APS + (uint32_t)rowA * 128;
  const int rBb = (lane & 7) + ((lane >> 4) & 1) * 8;
  const int hcB = (lane >> 3) & 1;
  const int subm = lane >> 3;
  const int rV = (lane & 7) + ((subm & 1) << 3);
  const int hsV = subm >> 1;

  float m0 = -1e30f, m1 = -1e30f, l0 = 0.f, l1 = 0.f;
  float O[16][4];
#pragma unroll
  for (int i = 0; i < 16; i++)
#pragma unroll
    for (int r = 0; r < 4; r++) O[i][r] = 0.f;

  for (int j = 0; j <= jmax; ++j) {
    __syncthreads();
    if (j < jmax) {
      KV_ISSUE(j + 1, (j + 1) & 1);
      asm volatile("cp.async.wait_group 1;" ::: "memory");
    } else {
      asm volatile("cp.async.wait_group 0;" ::: "memory");
    }
    __syncthreads();

    const uint32_t kvb = smb + AKV + (uint32_t)(j & 1) * AKVS;

    // ---- S = Qs K^T, 2-term (Q fp16 x (Kh + Kl)) ----
    float s[8][4];
#pragma unroll
    for (int ni = 0; ni < 8; ni++)
#pragma unroll
      for (int r = 0; r < 4; r++) s[ni][r] = 0.f;

#pragma unroll
    for (int kst = 0; kst < 8; ++kst) {
      unsigned qh[4];
      const uint32_t xa = (uint32_t)(((kst * 2 + hcA) ^ rxA) << 4);
      ldsm4(qh, aQ + xa);
#pragma unroll
      for (int p = 0; p < 4; ++p) {
        const int rb = p * 16 + rBb;
        const uint32_t ab =
            kvb + (uint32_t)rb * 256 + (uint32_t)(((kst * 2 + hcB) ^ (rb & 7)) << 4);
        unsigned kh[4], kl[4];
        ldsm4(kh, ab);
        ldsm4(kl, ab + 16384);
        const int n0i = p * 2;
        mma_f16(s[n0i],     qh, kh[0], kh[1]);
        mma_f16(s[n0i + 1], qh, kh[2], kh[3]);
        mma_f16(s[n0i],     qh, kl[0], kl[1]);
        mma_f16(s[n0i + 1], qh, kl[2], kl[3]);
      }
    }

    // ---- online softmax ----
    const int gr0 = q0 + w * 16 + g;
    const int gr1 = gr0 + 8;
    float tm0 = -1e30f, tm1 = -1e30f;
#pragma unroll
    for (int ni = 0; ni < 8; ni++) {
#pragma unroll
      for (int cc = 0; cc < 2; cc++) {
        int gc = j * 64 + ni * 8 + tg * 2 + cc;
        float v0 = s[ni][cc];
        float v1 = s[ni][2 + cc];
        if (gc > gr0) v0 = -1e30f;
        if (gc > gr1) v1 = -1e30f;
        s[ni][cc] = v0;
        s[ni][2 + cc] = v1;
        tm0 = fmaxf(tm0, v0);
        tm1 = fmaxf(tm1, v1);
      }
    }
    tm0 = fmaxf(tm0, __shfl_xor_sync(0xffffffffu, tm0, 1));
    tm0 = fmaxf(tm0, __shfl_xor_sync(0xffffffffu, tm0, 2));
    tm1 = fmaxf(tm1, __shfl_xor_sync(0xffffffffu, tm1, 1));
    tm1 = fmaxf(tm1, __shfl_xor_sync(0xffffffffu, tm1, 2));

    float nm0 = fmaxf(m0, tm0), nm1 = fmaxf(m1, tm1);
    float a0 = __expf(m0 - nm0), a1 = __expf(m1 - nm1);

    const uint32_t pr0 = APS + (uint32_t)(w * 16 + g) * 128;
    const uint32_t pr1 = pr0 + 1024;
    float ps0 = 0.f, ps1 = 0.f;
#pragma unroll
    for (int ni = 0; ni < 8; ni++) {
      float p00 = __expf(s[ni][0] - nm0);
      float p01 = __expf(s[ni][1] - nm0);
      float p10 = __expf(s[ni][2] - nm1);
      float p11 = __expf(s[ni][3] - nm1);
      ps0 += p00 + p01;
      ps1 += p10 + p11;
      const uint32_t px = (uint32_t)(((ni ^ g) << 4) + tg * 4);
      *reinterpret_cast<__half2*>(smc + pr0 + px) = __floats2half2_rn(p00, p01);
      *reinterpret_cast<__half2*>(smc + pr1 + px) = __floats2half2_rn(p10, p11);
    }
    ps0 += __shfl_xor_sync(0xffffffffu, ps0, 1);
    ps0 += __shfl_xor_sync(0xffffffffu, ps0, 2);
    ps1 += __shfl_xor_sync(0xffffffffu, ps1, 1);
    ps1 += __shfl_xor_sync(0xffffffffu, ps1, 2);

    l0 = l0 * a0 + ps0;
    l1 = l1 * a1 + ps1;
    m0 = nm0;
    m1 = nm1;
#pragma unroll
    for (int ni = 0; ni < 16; ni++) {
      O[ni][0] *= a0; O[ni][1] *= a0;
      O[ni][2] *= a1; O[ni][3] *= a1;
    }
    __syncwarp();

    // ---- O += P V (single pass, V fp16) ----
#pragma unroll
    for (int k2 = 0; k2 < 4; ++k2) {
      unsigned pf[4];
      ldsm4(pf, aP + (uint32_t)(((k2 * 2 + hcA) ^ rxA) << 4));
      const int rv = k2 * 16 + rV;
      const uint32_t vb = kvb + 32768 + (uint32_t)rv * 256;
      const int rxv = rv & 7;
      unsigned vf[8][4];
#pragma unroll
      for (int dg = 0; dg < 8; ++dg)
        ldsm4t(vf[dg], vb + (uint32_t)(((dg * 2 + hsV) ^ rxv) << 4));
#pragma unroll
      for (int dg = 0; dg < 8; ++dg) {
        mma_f16(O[dg * 2],     pf, vf[dg][0], vf[dg][1]);
        mma_f16(O[dg * 2 + 1], pf, vf[dg][2], vf[dg][3]);
      }
    }
  }
#undef KV_ISSUE

  // epilogue -> fp16 (feeds 1-term Wo GEMM)
  const float inv0 = 1.f / l0;
  const float inv1 = 1.f / l1;
  const int r0 = q0 + w * 16 + g;
#pragma unroll
  for (int ni = 0; ni < 16; ni++) {
    const int c = h * HD + ni * 8 + tg * 2;
    const size_t i0 = (size_t)r0 * HID + c;
    const size_t i1 = (size_t)(r0 + 8) * HID + c;
    *reinterpret_cast<__half2*>(oh + i0) =
        __floats2half2_rn(O[ni][0] * inv0, O[ni][1] * inv0);
    *reinterpret_cast<__half2*>(oh + i1) =
        __floats2half2_rn(O[ni][2] * inv1, O[ni][3] * inv1);
  }
}

// ---------------------------------------------------------------------------
// launch
// ---------------------------------------------------------------------------
extern "C" void kernel_launch(void* const* d_in, const int* in_sizes, int n_in,
                              void* d_out, int out_size) {
  (void)in_sizes; (void)n_in; (void)out_size;
  const int*   positions = (const int*)d_in[0];
  const float* hidden    = (const float*)d_in[1];
  const float* Wqkv      = (const float*)d_in[2];
  const float* Wo        = (const float*)d_in[3];
  float* out = (float*)d_out;

  __half *ah, *wq16, *wo16;
  cudaGetSymbolAddress((void**)&ah, g_ah);
  cudaGetSymbolAddress((void**)&wq16, g_wq16);
  cudaGetSymbolAddress((void**)&wo16, g_wo16);

  cudaFuncSetAttribute(gemm_h1t<0>, cudaFuncAttributeMaxDynamicSharedMemorySize,
                       GEMM_SMEM);
  cudaFuncSetAttribute(gemm_h1t<1>, cudaFuncAttributeMaxDynamicSharedMemorySize,
                       GEMM_SMEM);
  cudaFuncSetAttribute(attn4, cudaFuncAttributeMaxDynamicSharedMemorySize,
                       ATTN_SMEM);

  // 0) All prep in one launch (weight/activation converts + rope table)
  const size_t nprep = (size_t)HID * QKV_N / 4 + (size_t)HID * HID / 4 +
                       (size_t)T_SEQ * HID / 4 + (size_t)T_SEQ * 64;
  prep_all<<<(unsigned)((nprep + 255) / 256), 256>>>(
      (const float4*)Wqkv, (const float4*)Wo, (const float4*)hidden, positions);

  // 1) QKV projection with fused RoPE epilogue (writes g_qh/g_kh/g_kl/g_vh)
  gemm_h1t<1><<<dim3(QKV_N / 128, T_SEQ / 128), 256, GEMM_SMEM>>>(
      ah, wq16, nullptr, QKV_N, HID);
  // 2) Flash attention (writes fp16 into g_ah)
  attn4<<<dim3(NHEADS, T_SEQ / 256), 512, ATTN_SMEM>>>(ah);
  // 3) Output projection
  gemm_h1t<0><<<dim3(HID / 128, T_SEQ / 128), 256, GEMM_SMEM>>>(
      ah, wo16, out, HID, HID);
}